// round 12
// baseline (speedup 1.0000x reference)
#include <cuda_runtime.h>
#include <cuda_fp16.h>
#include <math.h>
#include <stdint.h>

#define B_   16384
#define H_   512
#define FF_  2048
#define OUT_ 4
#define HOR_ 5

// ---- scratch (device globals; no allocation) ----
__device__ float  g_h1[B_ * H_];
__device__ float  g_hx[B_ * H_];
__device__ float  g_xy[B_ * OUT_];
// fp16 copies (GEMM operands)
__device__ __half g_h1h[B_ * H_];
__device__ __half g_h2h[B_ * H_];
__device__ __half g_hxh[B_ * H_];
__device__ __half g_hxRh[B_ * H_];
__device__ __half g_ptfh[B_ * H_];
__device__ __half g_whhh[3 * H_ * H_];
__device__ __half g_wfch[H_ * 2 * H_];
__device__ __half g_w1h[FF_ * H_];

// ============================================================
// helpers
// ============================================================
__device__ __forceinline__ void mma_f16(float c[4], const uint32_t a[4],
                                        const uint32_t b[2]) {
    asm volatile(
        "mma.sync.aligned.m16n8k16.row.col.f32.f16.f16.f32 "
        "{%0,%1,%2,%3}, {%4,%5,%6,%7}, {%8,%9}, {%0,%1,%2,%3};"
        : "+f"(c[0]), "+f"(c[1]), "+f"(c[2]), "+f"(c[3])
        : "r"(a[0]), "r"(a[1]), "r"(a[2]), "r"(a[3]),
          "r"(b[0]), "r"(b[1]));
}

__device__ __forceinline__ void ldsm_x4(uint32_t r[4], uint32_t saddr) {
    asm volatile("ldmatrix.sync.aligned.m8n8.x4.shared.b16 {%0,%1,%2,%3}, [%4];"
                 : "=r"(r[0]), "=r"(r[1]), "=r"(r[2]), "=r"(r[3])
                 : "r"(saddr));
}

__device__ __forceinline__ void cp16(void* smem_ptr, const void* gsrc) {
    uint32_t a = (uint32_t)__cvta_generic_to_shared(smem_ptr);
    asm volatile("cp.async.cg.shared.global [%0], [%1], 16;"
                 :: "r"(a), "l"(gsrc));
}

#define CP_COMMIT() asm volatile("cp.async.commit_group;" ::: "memory")
#define CP_WAIT(n)  asm volatile("cp.async.wait_group %0;" :: "n"(n) : "memory")

__device__ __forceinline__ float sigmoidf_(float x) {
    return 1.f / (1.f + expf(-x));
}

// ============================================================
// prep kernels
// ============================================================
__global__ void cvt_kernel(const float* __restrict__ src,
                           __half* __restrict__ dst, int n4) {
    int i = blockIdx.x * blockDim.x + threadIdx.x;
    if (i < n4) {
        float4 v = reinterpret_cast<const float4*>(src)[i];
        reinterpret_cast<__half2*>(dst)[i * 2]     = __floats2half2_rn(v.x, v.y);
        reinterpret_cast<__half2*>(dst)[i * 2 + 1] = __floats2half2_rn(v.z, v.w);
    }
}

__global__ void zero_kernel(float* __restrict__ p, int n) {
    int i = blockIdx.x * blockDim.x + threadIdx.x;
    if (i < n) p[i] = 0.f;
}

#define SMSH 40   // W/A tile row pitch in halves: 32 + 8 pad (80B)

// ============================================================
// Gate-fused HH GEMM (fp16, ldmatrix, 3-stage cp.async).
// grid (B/128, 512/64).  256 threads, warp tile 32x32 per gate.
// ============================================================
#define HH_STAGE_H (320 * SMSH)
#define HH_SMEM_BYTES (3u * HH_STAGE_H * 2u)

__global__ void __launch_bounds__(256)
hh_fused(const __half* __restrict__ Ah, const __half* __restrict__ Whh,
         const float* __restrict__ hf, const float* __restrict__ x, int xstride,
         const float* __restrict__ w_ih, const float* __restrict__ b_ih,
         const float* __restrict__ b_hh,
         float* __restrict__ hout, __half* __restrict__ houth)
{
    extern __shared__ __half smh[];

    const int tid  = threadIdx.x;
    const int warp = tid >> 5;
    const int lane = tid & 31;
    const int gid  = lane >> 2;
    const int tig  = lane & 3;
    const int wm   = warp >> 1;
    const int wn   = warp & 1;
    const int bm   = blockIdx.x * 128;
    const int bn   = blockIdx.y * 64;

    const uint32_t sbase = (uint32_t)__cvta_generic_to_shared(smh);
    const int la_row = ((lane & 8) ? 8 : 0) + (lane & 7);
    const int la_k   = (lane & 16) ? 8 : 0;
    const int lb_n   = ((lane & 16) ? 8 : 0) + (lane & 7);
    const int lb_k   = (lane & 8) ? 8 : 0;

    float acc[3][2][4][4];
#pragma unroll
    for (int g = 0; g < 3; g++)
#pragma unroll
        for (int i = 0; i < 2; i++)
#pragma unroll
            for (int j = 0; j < 4; j++)
#pragma unroll
                for (int r = 0; r < 4; r++) acc[g][i][j][r] = 0.f;

    auto issue = [&](int t) {
        const int s  = t % 3;
        const int k0 = t * 32;
        __half* base = smh + s * HH_STAGE_H;
#pragma unroll
        for (int it = 0; it < 2; it++) {
            int lin = tid + it * 256;
            int row = lin >> 2, j = lin & 3;
            cp16(&base[row * SMSH + j * 8],
                 &Ah[(size_t)(bm + row) * 512 + k0 + j * 8]);
        }
#pragma unroll
        for (int it = 0; it < 3; it++) {
            int lin = tid + it * 256;
            int row = lin >> 2, j = lin & 3;
            int g = row >> 6, lr = row & 63;
            cp16(&base[(128 + row) * SMSH + j * 8],
                 &Whh[(size_t)(g * 512 + bn + lr) * 512 + k0 + j * 8]);
        }
        CP_COMMIT();
    };

    issue(0); issue(1); issue(2);

    for (int t = 0; t < 16; t++) {
        const int rem = 15 - t;
        if (rem >= 2)      CP_WAIT(2);
        else if (rem == 1) CP_WAIT(1);
        else               CP_WAIT(0);
        __syncthreads();

        const uint32_t st = sbase + (uint32_t)((t % 3) * HH_STAGE_H) * 2u;

#pragma unroll
        for (int kk = 0; kk < 2; kk++) {
            uint32_t afr[2][4];
#pragma unroll
            for (int i = 0; i < 2; i++)
                ldsm_x4(afr[i], st + (uint32_t)(
                    (wm * 32 + i * 16 + la_row) * SMSH + kk * 16 + la_k) * 2u);
            uint32_t bfr[3][4][2];
#pragma unroll
            for (int g = 0; g < 3; g++)
#pragma unroll
                for (int jp = 0; jp < 2; jp++) {
                    uint32_t r[4];
                    ldsm_x4(r, st + (uint32_t)(
                        (128 + g * 64 + wn * 32 + jp * 16 + lb_n) * SMSH
                        + kk * 16 + lb_k) * 2u);
                    bfr[g][jp * 2][0]     = r[0]; bfr[g][jp * 2][1]     = r[1];
                    bfr[g][jp * 2 + 1][0] = r[2]; bfr[g][jp * 2 + 1][1] = r[3];
                }
#pragma unroll
            for (int g = 0; g < 3; g++)
#pragma unroll
                for (int i = 0; i < 2; i++)
#pragma unroll
                    for (int j = 0; j < 4; j++)
                        mma_f16(acc[g][i][j], afr[i], bfr[g][j]);
        }
        __syncthreads();
        if (t + 3 < 16) issue(t + 3);
    }

    // ---- fused gate epilogue ----
#pragma unroll
    for (int i = 0; i < 2; i++) {
        const int r0 = bm + wm * 32 + i * 16 + gid;
        const int r1 = r0 + 8;
        const float4 xv0 = *reinterpret_cast<const float4*>(&x[(size_t)r0 * xstride]);
        const float4 xv1 = *reinterpret_cast<const float4*>(&x[(size_t)r1 * xstride]);
#pragma unroll
        for (int j = 0; j < 4; j++) {
            const int col = bn + wn * 32 + j * 8 + tig * 2;
            const float2 hp0 = *reinterpret_cast<const float2*>(&hf[(size_t)r0 * 512 + col]);
            const float2 hp1 = *reinterpret_cast<const float2*>(&hf[(size_t)r1 * 512 + col]);
            float res[2][2];
#pragma unroll
            for (int c = 0; c < 2; c++) {
                const int cc = col + c;
                const float4 wr  = *reinterpret_cast<const float4*>(&w_ih[(size_t)cc * 4]);
                const float4 wz  = *reinterpret_cast<const float4*>(&w_ih[(size_t)(cc + 512) * 4]);
                const float4 wnn = *reinterpret_cast<const float4*>(&w_ih[(size_t)(cc + 1024) * 4]);
                const float bir = b_ih[cc], biz = b_ih[cc + 512], bin = b_ih[cc + 1024];
                const float bhr = b_hh[cc], bhz = b_hh[cc + 512], bhn = b_hh[cc + 1024];
#pragma unroll
                for (int rr = 0; rr < 2; rr++) {
                    const float4 xv = rr ? xv1 : xv0;
                    float gir = bir + xv.x*wr.x + xv.y*wr.y + xv.z*wr.z + xv.w*wr.w;
                    float giz = biz + xv.x*wz.x + xv.y*wz.y + xv.z*wz.z + xv.w*wz.w;
                    float gin = bin + xv.x*wnn.x + xv.y*wnn.y + xv.z*wnn.z + xv.w*wnn.w;
                    float ghr = acc[0][i][j][rr * 2 + c] + bhr;
                    float ghz = acc[1][i][j][rr * 2 + c] + bhz;
                    float ghn = acc[2][i][j][rr * 2 + c] + bhn;
                    float rg = sigmoidf_(gir + ghr);
                    float zg = sigmoidf_(giz + ghz);
                    float ng = tanhf(gin + rg * ghn);
                    float hprev = rr ? (c ? hp1.y : hp1.x) : (c ? hp0.y : hp0.x);
                    res[rr][c] = (1.f - zg) * ng + zg * hprev;
                }
            }
            if (hout) {
                *reinterpret_cast<float2*>(&hout[(size_t)r0 * 512 + col])
                    = make_float2(res[0][0], res[0][1]);
                *reinterpret_cast<float2*>(&hout[(size_t)r1 * 512 + col])
                    = make_float2(res[1][0], res[1][1]);
            }
            *reinterpret_cast<__half2*>(&houth[(size_t)r0 * 512 + col])
                = __floats2half2_rn(res[0][0], res[0][1]);
            *reinterpret_cast<__half2*>(&houth[(size_t)r1 * 512 + col])
                = __floats2half2_rn(res[1][0], res[1][1]);
        }
    }
}

// ============================================================
// fc GEMM (3-stage): hx = concat(h1h,h2h) @ wfch^T + b_fc
// TRIPLE write: hx fp32, hxh fp16, hxRh relu fp16.
// ============================================================
#define TILE_H (128 * SMSH)
#define GC_SMEM_BYTES (6u * TILE_H * 2u)

__global__ void __launch_bounds__(256)
gemm_fc(const __half* __restrict__ A, const __half* __restrict__ A2,
        const __half* __restrict__ W, const float* __restrict__ bias,
        float* __restrict__ C, __half* __restrict__ Ch, __half* __restrict__ Chr)
{
    extern __shared__ __half smh[];
    const int K = 1024, N = 512;

    const int tid  = threadIdx.x;
    const int warp = tid >> 5;
    const int lane = tid & 31;
    const int gid  = lane >> 2;
    const int tig  = lane & 3;
    const int wm   = warp >> 1;
    const int wn   = warp & 1;
    const int bm   = blockIdx.x * 128;
    const int bn   = blockIdx.y * 128;

    const uint32_t sbase = (uint32_t)__cvta_generic_to_shared(smh);
    const int la_row = ((lane & 8) ? 8 : 0) + (lane & 7);
    const int la_k   = (lane & 16) ? 8 : 0;
    const int lb_n   = ((lane & 16) ? 8 : 0) + (lane & 7);
    const int lb_k   = (lane & 8) ? 8 : 0;

    float acc[2][8][4];
#pragma unroll
    for (int i = 0; i < 2; i++)
#pragma unroll
        for (int j = 0; j < 8; j++)
#pragma unroll
            for (int r = 0; r < 4; r++) acc[i][j][r] = 0.f;

    auto issue_tile = [&](int t) {
        const int s  = t % 3;
        const int k0 = t * 32;
        __half* sAh = smh + s * TILE_H;
        __half* sWh = smh + (3 + s) * TILE_H;
#pragma unroll
        for (int it = 0; it < 2; it++) {
            int lin = tid + it * 256;
            int row = lin >> 2, j = lin & 3;
            cp16(&sWh[row * SMSH + j * 8], &W[(size_t)(bn + row) * K + k0 + j * 8]);
            const __half* asrc = (k0 < 512)
                ? &A [(size_t)(bm + row) * 512 + k0 + j * 8]
                : &A2[(size_t)(bm + row) * 512 + (k0 - 512) + j * 8];
            cp16(&sAh[row * SMSH + j * 8], asrc);
        }
        CP_COMMIT();
    };

    const int T = K >> 5;    // 32
    issue_tile(0); issue_tile(1); issue_tile(2);

    for (int t = 0; t < T; t++) {
        const int rem = T - 1 - t;
        if (rem >= 2)      CP_WAIT(2);
        else if (rem == 1) CP_WAIT(1);
        else               CP_WAIT(0);
        __syncthreads();

        const uint32_t stA = sbase + (uint32_t)((t % 3) * TILE_H) * 2u;
        const uint32_t stW = sbase + (uint32_t)((3 + t % 3) * TILE_H) * 2u;

#pragma unroll
        for (int kk = 0; kk < 2; kk++) {
            uint32_t afr[2][4];
#pragma unroll
            for (int i = 0; i < 2; i++)
                ldsm_x4(afr[i], stA + (uint32_t)(
                    (wm * 32 + i * 16 + la_row) * SMSH + kk * 16 + la_k) * 2u);
            uint32_t bfr[8][2];
#pragma unroll
            for (int jp = 0; jp < 4; jp++) {
                uint32_t r[4];
                ldsm_x4(r, stW + (uint32_t)(
                    (wn * 64 + jp * 16 + lb_n) * SMSH + kk * 16 + lb_k) * 2u);
                bfr[jp * 2][0]     = r[0]; bfr[jp * 2][1]     = r[1];
                bfr[jp * 2 + 1][0] = r[2]; bfr[jp * 2 + 1][1] = r[3];
            }
#pragma unroll
            for (int i = 0; i < 2; i++)
#pragma unroll
                for (int j = 0; j < 8; j++)
                    mma_f16(acc[i][j], afr[i], bfr[j]);
        }
        __syncthreads();
        if (t + 3 < T) issue_tile(t + 3);
    }

#pragma unroll
    for (int i = 0; i < 2; i++) {
        int row0 = bm + wm * 32 + i * 16 + gid;
#pragma unroll
        for (int j = 0; j < 8; j++) {
            int col = bn + wn * 64 + j * 8 + tig * 2;
            float b0 = bias[col], b1v = bias[col + 1];
            float v0 = acc[i][j][0] + b0;
            float v1 = acc[i][j][1] + b1v;
            float v2 = acc[i][j][2] + b0;
            float v3 = acc[i][j][3] + b1v;
            *reinterpret_cast<float2*>(&C[(size_t)row0 * N + col]) = make_float2(v0, v1);
            *reinterpret_cast<float2*>(&C[(size_t)(row0 + 8) * N + col]) = make_float2(v2, v3);
            *reinterpret_cast<__half2*>(&Ch[(size_t)row0 * N + col])
                = __floats2half2_rn(v0, v1);
            *reinterpret_cast<__half2*>(&Ch[(size_t)(row0 + 8) * N + col])
                = __floats2half2_rn(v2, v3);
            *reinterpret_cast<__half2*>(&Chr[(size_t)row0 * N + col])
                = __floats2half2_rn(fmaxf(v0, 0.f), fmaxf(v1, 0.f));
            *reinterpret_cast<__half2*>(&Chr[(size_t)(row0 + 8) * N + col])
                = __floats2half2_rn(fmaxf(v2, 0.f), fmaxf(v3, 0.f));
        }
    }
}

// ============================================================
// Persistent MLP: grid (B/128) = 128 CTAs, one wave.
// A (128x512 fp16) + w2 (4x2048 f32) resident in smem; W1 tiles
// double-buffered.  Loops all 16 n-tiles x 16 k-tiles, contracts a1
// against w2 into registers, then writes xy += dxy + b2 and out[:,step].
// ============================================================
#define APITCH 520                              // 512 + 8 pad halves
#define MLP_A_BYTES   (128 * APITCH * 2)        // 133,120
#define MLP_W_BYTES   (2 * TILE_H * 2)          // 20,480
#define MLP_SW2_BYTES (4 * 2048 * 4)            // 32,768
#define MLP_SDXY_BYTES (128 * 4 * 4)            // 2,048
#define MLP_SMEM_BYTES (MLP_A_BYTES + MLP_W_BYTES + MLP_SW2_BYTES + MLP_SDXY_BYTES)

__global__ void __launch_bounds__(256)
gemm_mlp_persist(const __half* __restrict__ A, const __half* __restrict__ W,
                 const float* __restrict__ b1g, const float* __restrict__ w2,
                 const float* __restrict__ b2, float* __restrict__ xy,
                 float* __restrict__ out, int step)
{
    extern __shared__ char smraw[];
    __half* sA   = (__half*)smraw;
    __half* sW   = (__half*)(smraw + MLP_A_BYTES);
    float*  sw2  = (float*)(smraw + MLP_A_BYTES + MLP_W_BYTES);
    float*  sdxy = (float*)(smraw + MLP_A_BYTES + MLP_W_BYTES + MLP_SW2_BYTES);

    const int tid  = threadIdx.x;
    const int warp = tid >> 5;
    const int lane = tid & 31;
    const int gid  = lane >> 2;
    const int tig  = lane & 3;
    const int wm   = warp >> 1;
    const int wn   = warp & 1;
    const int bm   = blockIdx.x * 128;

    const uint32_t saA = (uint32_t)__cvta_generic_to_shared(sA);
    const uint32_t saW = (uint32_t)__cvta_generic_to_shared(sW);
    const int la_row = ((lane & 8) ? 8 : 0) + (lane & 7);
    const int la_k   = (lane & 16) ? 8 : 0;
    const int lb_n   = ((lane & 16) ? 8 : 0) + (lane & 7);
    const int lb_k   = (lane & 8) ? 8 : 0;

    // resident loads: A (group 0)
    for (int c = tid; c < 128 * 64; c += 256) {       // 64 x 16B chunks per row
        int row = c >> 6, j = c & 63;
        cp16(&sA[row * APITCH + j * 8], &A[(size_t)(bm + row) * 512 + j * 8]);
    }
    CP_COMMIT();
    // w2 + sdxy via plain ld/st (visible after later syncthreads)
    for (int i = tid; i < 4 * 2048; i += 256)
        sw2[i] = w2[i];
    for (int i = tid; i < 512; i += 256)
        sdxy[i] = 0.f;

    auto issueW = [&](int tt) {
        const int n = tt >> 4, k = tt & 15;
        __half* dst = sW + (tt & 1) * TILE_H;
#pragma unroll
        for (int it = 0; it < 2; it++) {
            int lin = tid + it * 256;
            int row = lin >> 2, j = lin & 3;
            cp16(&dst[row * SMSH + j * 8],
                 &W[(size_t)(n * 128 + row) * 512 + k * 32 + j * 8]);
        }
        CP_COMMIT();
    };

    issueW(0); issueW(1);

    float p[2][2][4];
#pragma unroll
    for (int i = 0; i < 2; i++)
#pragma unroll
        for (int rr = 0; rr < 2; rr++)
#pragma unroll
            for (int o = 0; o < 4; o++) p[i][rr][o] = 0.f;

    float acc[2][8][4];

    for (int tt = 0; tt < 256; tt++) {
        if (tt < 255) CP_WAIT(1); else CP_WAIT(0);
        __syncthreads();

        if ((tt & 15) == 0) {
#pragma unroll
            for (int i = 0; i < 2; i++)
#pragma unroll
                for (int j = 0; j < 8; j++)
#pragma unroll
                    for (int r = 0; r < 4; r++) acc[i][j][r] = 0.f;
        }

        const int kt = tt & 15;
        const uint32_t stW = saW + (uint32_t)((tt & 1) * TILE_H) * 2u;

#pragma unroll
        for (int kk = 0; kk < 2; kk++) {
            uint32_t afr[2][4];
#pragma unroll
            for (int i = 0; i < 2; i++)
                ldsm_x4(afr[i], saA + (uint32_t)(
                    (wm * 32 + i * 16 + la_row) * APITCH
                    + kt * 32 + kk * 16 + la_k) * 2u);
            uint32_t bfr[8][2];
#pragma unroll
            for (int jp = 0; jp < 4; jp++) {
                uint32_t r[4];
                ldsm_x4(r, stW + (uint32_t)(
                    (wn * 64 + jp * 16 + lb_n) * SMSH + kk * 16 + lb_k) * 2u);
                bfr[jp * 2][0]     = r[0]; bfr[jp * 2][1]     = r[1];
                bfr[jp * 2 + 1][0] = r[2]; bfr[jp * 2 + 1][1] = r[3];
            }
#pragma unroll
            for (int i = 0; i < 2; i++)
#pragma unroll
                for (int j = 0; j < 8; j++)
                    mma_f16(acc[i][j], afr[i], bfr[j]);
        }
        __syncthreads();
        if (tt + 2 < 256) issueW(tt + 2);

        if (kt == 15) {
            // contract finished a1 n-tile into p
            const int nb = (tt >> 4) * 128;
#pragma unroll
            for (int i = 0; i < 2; i++)
#pragma unroll
                for (int j = 0; j < 8; j++) {
                    const int lc = nb + wn * 64 + j * 8 + tig * 2;
                    const float bb0 = b1g[lc], bb1 = b1g[lc + 1];
                    const float a00 = fmaxf(acc[i][j][0] + bb0, 0.f);
                    const float a01 = fmaxf(acc[i][j][1] + bb1, 0.f);
                    const float a10 = fmaxf(acc[i][j][2] + bb0, 0.f);
                    const float a11 = fmaxf(acc[i][j][3] + bb1, 0.f);
#pragma unroll
                    for (int o = 0; o < 4; o++) {
                        const float w0 = sw2[o * 2048 + lc];
                        const float w1 = sw2[o * 2048 + lc + 1];
                        p[i][0][o] += a00 * w0 + a01 * w1;
                        p[i][1][o] += a10 * w0 + a11 * w1;
                    }
                }
        }
    }

    // ---- reduce p and write xy / out ----
#pragma unroll
    for (int i = 0; i < 2; i++)
#pragma unroll
        for (int rr = 0; rr < 2; rr++)
#pragma unroll
            for (int o = 0; o < 4; o++) {
                float v = p[i][rr][o];
                v += __shfl_xor_sync(0xFFFFFFFFu, v, 1);
                v += __shfl_xor_sync(0xFFFFFFFFu, v, 2);
                p[i][rr][o] = v;
            }
    if (tig == 0) {
#pragma unroll
        for (int i = 0; i < 2; i++)
#pragma unroll
            for (int rr = 0; rr < 2; rr++) {
                const int row = wm * 32 + i * 16 + rr * 8 + gid;
#pragma unroll
                for (int o = 0; o < 4; o++)
                    atomicAdd(&sdxy[row * 4 + o], p[i][rr][o]);
            }
    }
    __syncthreads();
    for (int r = tid; r < 128; r += 256) {
        const int gr = bm + r;
        float4 xv = reinterpret_cast<float4*>(xy)[gr];
        xv.x += sdxy[r * 4 + 0] + b2[0];
        xv.y += sdxy[r * 4 + 1] + b2[1];
        xv.z += sdxy[r * 4 + 2] + b2[2];
        xv.w += sdxy[r * 4 + 3] + b2[3];
        reinterpret_cast<float4*>(xy)[gr] = xv;
        reinterpret_cast<float4*>(out)[(size_t)gr * HOR_ + step] = xv;
    }
}

// ============================================================
// Launch
// ============================================================
extern "C" void kernel_launch(void* const* d_in, const int* in_sizes, int n_in,
                              void* d_out, int out_size)
{
    const float* pv   = (const float*)d_in[0];
    const float* ptf  = (const float*)d_in[1];
    const float* w_ih = (const float*)d_in[2];
    const float* w_hh = (const float*)d_in[3];
    const float* b_ih = (const float*)d_in[4];
    const float* b_hh = (const float*)d_in[5];
    const float* w_fc = (const float*)d_in[6];
    const float* b_fc = (const float*)d_in[7];
    const float* w1   = (const float*)d_in[8];
    const float* b1   = (const float*)d_in[9];
    const float* w2   = (const float*)d_in[10];
    const float* b2   = (const float*)d_in[11];
    float* out = (float*)d_out;

    float *h1, *hx, *xy;
    __half *h1h, *h2h, *hxh, *hxRh, *ptfh, *whhh, *wfch, *w1h;
    cudaGetSymbolAddress((void**)&h1,   g_h1);
    cudaGetSymbolAddress((void**)&hx,   g_hx);
    cudaGetSymbolAddress((void**)&xy,   g_xy);
    cudaGetSymbolAddress((void**)&h1h,  g_h1h);
    cudaGetSymbolAddress((void**)&h2h,  g_h2h);
    cudaGetSymbolAddress((void**)&hxh,  g_hxh);
    cudaGetSymbolAddress((void**)&hxRh, g_hxRh);
    cudaGetSymbolAddress((void**)&ptfh, g_ptfh);
    cudaGetSymbolAddress((void**)&whhh, g_whhh);
    cudaGetSymbolAddress((void**)&wfch, g_wfch);
    cudaGetSymbolAddress((void**)&w1h,  g_w1h);

    cudaFuncSetAttribute(hh_fused,
        cudaFuncAttributeMaxDynamicSharedMemorySize, HH_SMEM_BYTES);
    cudaFuncSetAttribute(gemm_fc,
        cudaFuncAttributeMaxDynamicSharedMemorySize, GC_SMEM_BYTES);
    cudaFuncSetAttribute(gemm_mlp_persist,
        cudaFuncAttributeMaxDynamicSharedMemorySize, MLP_SMEM_BYTES);

    // ---- prep ----
    cvt_kernel<<<(3 * H_ * H_ / 4 + 255) / 256, 256>>>(w_hh, whhh, 3 * H_ * H_ / 4);
    cvt_kernel<<<(H_ * 2 * H_ / 4 + 255) / 256, 256>>>(w_fc, wfch, H_ * 2 * H_ / 4);
    cvt_kernel<<<(FF_ * H_ / 4 + 255) / 256, 256>>>(w1, w1h, FF_ * H_ / 4);
    cvt_kernel<<<(B_ * H_ / 4 + 255) / 256, 256>>>(ptf, ptfh, B_ * H_ / 4);
    zero_kernel<<<(B_ * OUT_ + 255) / 256, 256>>>(xy, B_ * OUT_);

    const dim3 gridHH(B_ / 128, H_ / 64);      // (128, 8)
    const dim3 gridFC(B_ / 128, H_ / 128);     // (128, 4)

    for (int step = 0; step < HOR_; step++) {
        const __half* hxin_h = (step == 0) ? ptfh : hxh;
        const float*  hxin_f = (step == 0) ? ptf  : hx;

        hh_fused<<<gridHH, 256, HH_SMEM_BYTES>>>(
            hxin_h, whhh, hxin_f, xy, OUT_, w_ih, b_ih, b_hh, h1, h1h);

        hh_fused<<<gridHH, 256, HH_SMEM_BYTES>>>(
            h1h, whhh, h1, pv + step * OUT_, HOR_ * OUT_, w_ih, b_ih, b_hh,
            nullptr, h2h);

        gemm_fc<<<gridFC, 256, GC_SMEM_BYTES>>>(h1h, h2h, wfch, b_fc,
                                                hx, hxh, hxRh);

        gemm_mlp_persist<<<B_ / 128, 256, MLP_SMEM_BYTES>>>(
            hxRh, w1h, b1, w2, b2, xy, out, step);
    }
}

// round 13
// speedup vs baseline: 1.1495x; 1.1495x over previous
#include <cuda_runtime.h>
#include <cuda_fp16.h>
#include <math.h>
#include <stdint.h>

#define B_   16384
#define H_   512
#define FF_  2048
#define OUT_ 4
#define HOR_ 5

// ---- scratch (device globals; no allocation) ----
__device__ float  g_h1[B_ * H_];
__device__ float  g_hx[B_ * H_];
__device__ float  g_xy[B_ * OUT_];
__device__ float  g_dxy[B_ * OUT_];
// fp16 copies (GEMM operands)
__device__ __half g_h1h[B_ * H_];
__device__ __half g_h2h[B_ * H_];
__device__ __half g_hxh[B_ * H_];
__device__ __half g_hxRh[B_ * H_];
__device__ __half g_ptfh[B_ * H_];
__device__ __half g_whhh[3 * H_ * H_];
__device__ __half g_wfch[H_ * 2 * H_];
__device__ __half g_w1h[FF_ * H_];

// ============================================================
// helpers
// ============================================================
__device__ __forceinline__ void mma_f16(float c[4], const uint32_t a[4],
                                        const uint32_t b[2]) {
    asm volatile(
        "mma.sync.aligned.m16n8k16.row.col.f32.f16.f16.f32 "
        "{%0,%1,%2,%3}, {%4,%5,%6,%7}, {%8,%9}, {%0,%1,%2,%3};"
        : "+f"(c[0]), "+f"(c[1]), "+f"(c[2]), "+f"(c[3])
        : "r"(a[0]), "r"(a[1]), "r"(a[2]), "r"(a[3]),
          "r"(b[0]), "r"(b[1]));
}

__device__ __forceinline__ void ldsm_x4(uint32_t r[4], uint32_t saddr) {
    asm volatile("ldmatrix.sync.aligned.m8n8.x4.shared.b16 {%0,%1,%2,%3}, [%4];"
                 : "=r"(r[0]), "=r"(r[1]), "=r"(r[2]), "=r"(r[3])
                 : "r"(saddr));
}

__device__ __forceinline__ void cp16(void* smem_ptr, const void* gsrc) {
    uint32_t a = (uint32_t)__cvta_generic_to_shared(smem_ptr);
    asm volatile("cp.async.cg.shared.global [%0], [%1], 16;"
                 :: "r"(a), "l"(gsrc));
}

#define CP_COMMIT() asm volatile("cp.async.commit_group;" ::: "memory")
#define CP_WAIT(n)  asm volatile("cp.async.wait_group %0;" :: "n"(n) : "memory")

__device__ __forceinline__ float sigmoidf_(float x) {
    return 1.f / (1.f + expf(-x));
}

// ============================================================
// prep kernels
// ============================================================
__global__ void cvt_kernel(const float* __restrict__ src,
                           __half* __restrict__ dst, int n4) {
    int i = blockIdx.x * blockDim.x + threadIdx.x;
    if (i < n4) {
        float4 v = reinterpret_cast<const float4*>(src)[i];
        reinterpret_cast<__half2*>(dst)[i * 2]     = __floats2half2_rn(v.x, v.y);
        reinterpret_cast<__half2*>(dst)[i * 2 + 1] = __floats2half2_rn(v.z, v.w);
    }
}

__global__ void zero_kernel(float* __restrict__ p, int n) {
    int i = blockIdx.x * blockDim.x + threadIdx.x;
    if (i < n) p[i] = 0.f;
}

#define SMSH 40   // smem row pitch in halves: 32 + 8 pad (80B)

// ============================================================
// Gate-fused HH GEMM (fp16, ldmatrix, 3-stage cp.async, 2 CTAs/SM).
// grid (B/128, 512/64).  256 threads, warp tile 32x32 per gate.
// B-fragments consumed gate-sequentially to keep regs <= 128.
// ============================================================
#define HH_STAGE_H (320 * SMSH)
#define HH_SMEM_BYTES (3u * HH_STAGE_H * 2u)

__global__ void __launch_bounds__(256, 2)
hh_fused(const __half* __restrict__ Ah, const __half* __restrict__ Whh,
         const float* __restrict__ hf, const float* __restrict__ x, int xstride,
         const float* __restrict__ w_ih, const float* __restrict__ b_ih,
         const float* __restrict__ b_hh,
         float* __restrict__ hout, __half* __restrict__ houth)
{
    extern __shared__ __half smh[];

    const int tid  = threadIdx.x;
    const int warp = tid >> 5;
    const int lane = tid & 31;
    const int gid  = lane >> 2;
    const int tig  = lane & 3;
    const int wm   = warp >> 1;
    const int wn   = warp & 1;
    const int bm   = blockIdx.x * 128;
    const int bn   = blockIdx.y * 64;

    const uint32_t sbase = (uint32_t)__cvta_generic_to_shared(smh);
    const int la_row = ((lane & 8) ? 8 : 0) + (lane & 7);
    const int la_k   = (lane & 16) ? 8 : 0;
    const int lb_n   = ((lane & 16) ? 8 : 0) + (lane & 7);
    const int lb_k   = (lane & 8) ? 8 : 0;

    float acc[3][2][4][4];
#pragma unroll
    for (int g = 0; g < 3; g++)
#pragma unroll
        for (int i = 0; i < 2; i++)
#pragma unroll
            for (int j = 0; j < 4; j++)
#pragma unroll
                for (int r = 0; r < 4; r++) acc[g][i][j][r] = 0.f;

    auto issue = [&](int t) {
        const int s  = t % 3;
        const int k0 = t * 32;
        __half* base = smh + s * HH_STAGE_H;
#pragma unroll
        for (int it = 0; it < 2; it++) {
            int lin = tid + it * 256;
            int row = lin >> 2, j = lin & 3;
            cp16(&base[row * SMSH + j * 8],
                 &Ah[(size_t)(bm + row) * 512 + k0 + j * 8]);
        }
#pragma unroll
        for (int it = 0; it < 3; it++) {
            int lin = tid + it * 256;
            int row = lin >> 2, j = lin & 3;
            int g = row >> 6, lr = row & 63;
            cp16(&base[(128 + row) * SMSH + j * 8],
                 &Whh[(size_t)(g * 512 + bn + lr) * 512 + k0 + j * 8]);
        }
        CP_COMMIT();
    };

    issue(0); issue(1); issue(2);

    for (int t = 0; t < 16; t++) {
        const int rem = 15 - t;
        if (rem >= 2)      CP_WAIT(2);
        else if (rem == 1) CP_WAIT(1);
        else               CP_WAIT(0);
        __syncthreads();

        const uint32_t st = sbase + (uint32_t)((t % 3) * HH_STAGE_H) * 2u;

#pragma unroll
        for (int kk = 0; kk < 2; kk++) {
            uint32_t afr[2][4];
#pragma unroll
            for (int i = 0; i < 2; i++)
                ldsm_x4(afr[i], st + (uint32_t)(
                    (wm * 32 + i * 16 + la_row) * SMSH + kk * 16 + la_k) * 2u);
            // gate-sequential B consumption (live bfr = 8 regs)
#pragma unroll
            for (int g = 0; g < 3; g++) {
                uint32_t bfr[4][2];
#pragma unroll
                for (int jp = 0; jp < 2; jp++) {
                    uint32_t r[4];
                    ldsm_x4(r, st + (uint32_t)(
                        (128 + g * 64 + wn * 32 + jp * 16 + lb_n) * SMSH
                        + kk * 16 + lb_k) * 2u);
                    bfr[jp * 2][0]     = r[0]; bfr[jp * 2][1]     = r[1];
                    bfr[jp * 2 + 1][0] = r[2]; bfr[jp * 2 + 1][1] = r[3];
                }
#pragma unroll
                for (int i = 0; i < 2; i++)
#pragma unroll
                    for (int j = 0; j < 4; j++)
                        mma_f16(acc[g][i][j], afr[i], bfr[j]);
            }
        }
        __syncthreads();
        if (t + 3 < 16) issue(t + 3);
    }

    // ---- fused gate epilogue ----
#pragma unroll
    for (int i = 0; i < 2; i++) {
        const int r0 = bm + wm * 32 + i * 16 + gid;
        const int r1 = r0 + 8;
        const float4 xv0 = *reinterpret_cast<const float4*>(&x[(size_t)r0 * xstride]);
        const float4 xv1 = *reinterpret_cast<const float4*>(&x[(size_t)r1 * xstride]);
#pragma unroll
        for (int j = 0; j < 4; j++) {
            const int col = bn + wn * 32 + j * 8 + tig * 2;
            const float2 hp0 = *reinterpret_cast<const float2*>(&hf[(size_t)r0 * 512 + col]);
            const float2 hp1 = *reinterpret_cast<const float2*>(&hf[(size_t)r1 * 512 + col]);
            float res[2][2];
#pragma unroll
            for (int c = 0; c < 2; c++) {
                const int cc = col + c;
                const float4 wr  = *reinterpret_cast<const float4*>(&w_ih[(size_t)cc * 4]);
                const float4 wz  = *reinterpret_cast<const float4*>(&w_ih[(size_t)(cc + 512) * 4]);
                const float4 wnn = *reinterpret_cast<const float4*>(&w_ih[(size_t)(cc + 1024) * 4]);
                const float bir = b_ih[cc], biz = b_ih[cc + 512], bin = b_ih[cc + 1024];
                const float bhr = b_hh[cc], bhz = b_hh[cc + 512], bhn = b_hh[cc + 1024];
#pragma unroll
                for (int rr = 0; rr < 2; rr++) {
                    const float4 xv = rr ? xv1 : xv0;
                    float gir = bir + xv.x*wr.x + xv.y*wr.y + xv.z*wr.z + xv.w*wr.w;
                    float giz = biz + xv.x*wz.x + xv.y*wz.y + xv.z*wz.z + xv.w*wz.w;
                    float gin = bin + xv.x*wnn.x + xv.y*wnn.y + xv.z*wnn.z + xv.w*wnn.w;
                    float ghr = acc[0][i][j][rr * 2 + c] + bhr;
                    float ghz = acc[1][i][j][rr * 2 + c] + bhz;
                    float ghn = acc[2][i][j][rr * 2 + c] + bhn;
                    float rg = sigmoidf_(gir + ghr);
                    float zg = sigmoidf_(giz + ghz);
                    float ng = tanhf(gin + rg * ghn);
                    float hprev = rr ? (c ? hp1.y : hp1.x) : (c ? hp0.y : hp0.x);
                    res[rr][c] = (1.f - zg) * ng + zg * hprev;
                }
            }
            if (hout) {
                *reinterpret_cast<float2*>(&hout[(size_t)r0 * 512 + col])
                    = make_float2(res[0][0], res[0][1]);
                *reinterpret_cast<float2*>(&hout[(size_t)r1 * 512 + col])
                    = make_float2(res[1][0], res[1][1]);
            }
            *reinterpret_cast<__half2*>(&houth[(size_t)r0 * 512 + col])
                = __floats2half2_rn(res[0][0], res[0][1]);
            *reinterpret_cast<__half2*>(&houth[(size_t)r1 * 512 + col])
                = __floats2half2_rn(res[1][0], res[1][1]);
        }
    }
}

// ============================================================
// fc GEMM (3-stage): hx = concat(h1h,h2h) @ wfch^T + b_fc
// TRIPLE write: hx fp32, hxh fp16, hxRh relu fp16.
// ============================================================
#define TILE_H (128 * SMSH)
#define GC3_SMEM_BYTES (6u * TILE_H * 2u)
#define GC2_SMEM_BYTES (4u * TILE_H * 2u)

__global__ void __launch_bounds__(256, 2)
gemm_fc(const __half* __restrict__ A, const __half* __restrict__ A2,
        const __half* __restrict__ W, const float* __restrict__ bias,
        float* __restrict__ C, __half* __restrict__ Ch, __half* __restrict__ Chr)
{
    extern __shared__ __half smh[];
    const int K = 1024, N = 512;

    const int tid  = threadIdx.x;
    const int warp = tid >> 5;
    const int lane = tid & 31;
    const int gid  = lane >> 2;
    const int tig  = lane & 3;
    const int wm   = warp >> 1;
    const int wn   = warp & 1;
    const int bm   = blockIdx.x * 128;
    const int bn   = blockIdx.y * 128;

    const uint32_t sbase = (uint32_t)__cvta_generic_to_shared(smh);
    const int la_row = ((lane & 8) ? 8 : 0) + (lane & 7);
    const int la_k   = (lane & 16) ? 8 : 0;
    const int lb_n   = ((lane & 16) ? 8 : 0) + (lane & 7);
    const int lb_k   = (lane & 8) ? 8 : 0;

    float acc[2][8][4];
#pragma unroll
    for (int i = 0; i < 2; i++)
#pragma unroll
        for (int j = 0; j < 8; j++)
#pragma unroll
            for (int r = 0; r < 4; r++) acc[i][j][r] = 0.f;

    auto issue_tile = [&](int t) {
        const int s  = t % 3;
        const int k0 = t * 32;
        __half* sAh = smh + s * TILE_H;
        __half* sWh = smh + (3 + s) * TILE_H;
#pragma unroll
        for (int it = 0; it < 2; it++) {
            int lin = tid + it * 256;
            int row = lin >> 2, j = lin & 3;
            cp16(&sWh[row * SMSH + j * 8], &W[(size_t)(bn + row) * K + k0 + j * 8]);
            const __half* asrc = (k0 < 512)
                ? &A [(size_t)(bm + row) * 512 + k0 + j * 8]
                : &A2[(size_t)(bm + row) * 512 + (k0 - 512) + j * 8];
            cp16(&sAh[row * SMSH + j * 8], asrc);
        }
        CP_COMMIT();
    };

    const int T = K >> 5;
    issue_tile(0); issue_tile(1); issue_tile(2);

    for (int t = 0; t < T; t++) {
        const int rem = T - 1 - t;
        if (rem >= 2)      CP_WAIT(2);
        else if (rem == 1) CP_WAIT(1);
        else               CP_WAIT(0);
        __syncthreads();

        const uint32_t stA = sbase + (uint32_t)((t % 3) * TILE_H) * 2u;
        const uint32_t stW = sbase + (uint32_t)((3 + t % 3) * TILE_H) * 2u;

#pragma unroll
        for (int kk = 0; kk < 2; kk++) {
            uint32_t afr[2][4];
#pragma unroll
            for (int i = 0; i < 2; i++)
                ldsm_x4(afr[i], stA + (uint32_t)(
                    (wm * 32 + i * 16 + la_row) * SMSH + kk * 16 + la_k) * 2u);
            uint32_t bfr[8][2];
#pragma unroll
            for (int jp = 0; jp < 4; jp++) {
                uint32_t r[4];
                ldsm_x4(r, stW + (uint32_t)(
                    (wn * 64 + jp * 16 + lb_n) * SMSH + kk * 16 + lb_k) * 2u);
                bfr[jp * 2][0]     = r[0]; bfr[jp * 2][1]     = r[1];
                bfr[jp * 2 + 1][0] = r[2]; bfr[jp * 2 + 1][1] = r[3];
            }
#pragma unroll
            for (int i = 0; i < 2; i++)
#pragma unroll
                for (int j = 0; j < 8; j++)
                    mma_f16(acc[i][j], afr[i], bfr[j]);
        }
        __syncthreads();
        if (t + 3 < T) issue_tile(t + 3);
    }

#pragma unroll
    for (int i = 0; i < 2; i++) {
        int row0 = bm + wm * 32 + i * 16 + gid;
#pragma unroll
        for (int j = 0; j < 8; j++) {
            int col = bn + wn * 64 + j * 8 + tig * 2;
            float b0 = bias[col], b1v = bias[col + 1];
            float v0 = acc[i][j][0] + b0;
            float v1 = acc[i][j][1] + b1v;
            float v2 = acc[i][j][2] + b0;
            float v3 = acc[i][j][3] + b1v;
            *reinterpret_cast<float2*>(&C[(size_t)row0 * N + col]) = make_float2(v0, v1);
            *reinterpret_cast<float2*>(&C[(size_t)(row0 + 8) * N + col]) = make_float2(v2, v3);
            *reinterpret_cast<__half2*>(&Ch[(size_t)row0 * N + col])
                = __floats2half2_rn(v0, v1);
            *reinterpret_cast<__half2*>(&Ch[(size_t)(row0 + 8) * N + col])
                = __floats2half2_rn(v2, v3);
            *reinterpret_cast<__half2*>(&Chr[(size_t)row0 * N + col])
                = __floats2half2_rn(fmaxf(v0, 0.f), fmaxf(v1, 0.f));
            *reinterpret_cast<__half2*>(&Chr[(size_t)(row0 + 8) * N + col])
                = __floats2half2_rn(fmaxf(v2, 0.f), fmaxf(v3, 0.f));
        }
    }
}

// ============================================================
// MLP GEMM fused with w2 contraction (A = relu'd fp16)  [R10 proven]
// ============================================================
__global__ void __launch_bounds__(256, 2)
gemm_mlp(const __half* __restrict__ A, const __half* __restrict__ W,
         const float* __restrict__ b1g, const float* __restrict__ w2,
         float* __restrict__ dxy)
{
    extern __shared__ __half smh[];
    __shared__ float sw2[4][128];
    __shared__ float sdxy[128][4];
    const int K = 512;

    const int tid  = threadIdx.x;
    const int warp = tid >> 5;
    const int lane = tid & 31;
    const int gid  = lane >> 2;
    const int tig  = lane & 3;
    const int wm   = warp >> 1;
    const int wn   = warp & 1;
    const int bm   = blockIdx.x * 128;
    const int bn   = blockIdx.y * 128;

    const uint32_t sbase = (uint32_t)__cvta_generic_to_shared(smh);
    const int la_row = ((lane & 8) ? 8 : 0) + (lane & 7);
    const int la_k   = (lane & 16) ? 8 : 0;
    const int lb_n   = ((lane & 16) ? 8 : 0) + (lane & 7);
    const int lb_k   = (lane & 8) ? 8 : 0;

    for (int i = tid; i < 512; i += 256) {
        sw2[i >> 7][i & 127] = w2[(size_t)(i >> 7) * 2048 + bn + (i & 127)];
        reinterpret_cast<float*>(sdxy)[i] = 0.f;
    }

    float acc[2][8][4];
#pragma unroll
    for (int i = 0; i < 2; i++)
#pragma unroll
        for (int j = 0; j < 8; j++)
#pragma unroll
            for (int r = 0; r < 4; r++) acc[i][j][r] = 0.f;

    auto issue_tile = [&](int s, int k0) {
        __half* sAh = smh + s * TILE_H;
        __half* sWh = smh + 2 * TILE_H + s * TILE_H;
#pragma unroll
        for (int it = 0; it < 2; it++) {
            int lin = tid + it * 256;
            int row = lin >> 2, j = lin & 3;
            cp16(&sWh[row * SMSH + j * 8], &W[(size_t)(bn + row) * K + k0 + j * 8]);
            cp16(&sAh[row * SMSH + j * 8], &A[(size_t)(bm + row) * K + k0 + j * 8]);
        }
        CP_COMMIT();
    };

    const int T = K >> 5;
    issue_tile(0, 0);

    for (int t = 0; t < T; t++) {
        if (t + 1 < T) {
            issue_tile((t + 1) & 1, (t + 1) * 32);
            CP_WAIT(1);
        } else {
            CP_WAIT(0);
        }
        __syncthreads();

        const uint32_t stA = sbase + (uint32_t)((t & 1) * TILE_H) * 2u;
        const uint32_t stW = sbase + (uint32_t)((2 + (t & 1)) * TILE_H) * 2u;

#pragma unroll
        for (int kk = 0; kk < 2; kk++) {
            uint32_t afr[2][4];
#pragma unroll
            for (int i = 0; i < 2; i++)
                ldsm_x4(afr[i], stA + (uint32_t)(
                    (wm * 32 + i * 16 + la_row) * SMSH + kk * 16 + la_k) * 2u);
            uint32_t bfr[8][2];
#pragma unroll
            for (int jp = 0; jp < 4; jp++) {
                uint32_t r[4];
                ldsm_x4(r, stW + (uint32_t)(
                    (wn * 64 + jp * 16 + lb_n) * SMSH + kk * 16 + lb_k) * 2u);
                bfr[jp * 2][0]     = r[0]; bfr[jp * 2][1]     = r[1];
                bfr[jp * 2 + 1][0] = r[2]; bfr[jp * 2 + 1][1] = r[3];
            }
#pragma unroll
            for (int i = 0; i < 2; i++)
#pragma unroll
                for (int j = 0; j < 8; j++)
                    mma_f16(acc[i][j], afr[i], bfr[j]);
        }
        __syncthreads();
    }

    // ---- epilogue: contract a1 tile with w2 slice ----
    float p[2][2][4];
#pragma unroll
    for (int i = 0; i < 2; i++)
#pragma unroll
        for (int rr = 0; rr < 2; rr++)
#pragma unroll
            for (int o = 0; o < 4; o++) p[i][rr][o] = 0.f;

#pragma unroll
    for (int i = 0; i < 2; i++)
#pragma unroll
        for (int j = 0; j < 8; j++) {
            const int lc = wn * 64 + j * 8 + tig * 2;
            const float bb0 = b1g[bn + lc], bb1 = b1g[bn + lc + 1];
            const float a00 = fmaxf(acc[i][j][0] + bb0, 0.f);
            const float a01 = fmaxf(acc[i][j][1] + bb1, 0.f);
            const float a10 = fmaxf(acc[i][j][2] + bb0, 0.f);
            const float a11 = fmaxf(acc[i][j][3] + bb1, 0.f);
#pragma unroll
            for (int o = 0; o < 4; o++) {
                const float w0 = sw2[o][lc], w1 = sw2[o][lc + 1];
                p[i][0][o] += a00 * w0 + a01 * w1;
                p[i][1][o] += a10 * w0 + a11 * w1;
            }
        }

#pragma unroll
    for (int i = 0; i < 2; i++)
#pragma unroll
        for (int rr = 0; rr < 2; rr++)
#pragma unroll
            for (int o = 0; o < 4; o++) {
                float v = p[i][rr][o];
                v += __shfl_xor_sync(0xFFFFFFFFu, v, 1);
                v += __shfl_xor_sync(0xFFFFFFFFu, v, 2);
                p[i][rr][o] = v;
            }
    if (tig == 0) {
#pragma unroll
        for (int i = 0; i < 2; i++)
#pragma unroll
            for (int rr = 0; rr < 2; rr++) {
                const int row = wm * 32 + i * 16 + rr * 8 + gid;
#pragma unroll
                for (int o = 0; o < 4; o++)
                    atomicAdd(&sdxy[row][o], p[i][rr][o]);
            }
    }
    __syncthreads();
    for (int i = tid; i < 512; i += 256) {
        const int row = i >> 2, o = i & 3;
        atomicAdd(&dxy[(size_t)(bm + row) * 4 + o], sdxy[row][o]);
    }
}

// ============================================================
// readout: xy += dxy + b2; out[:, step] = xy; dxy = 0
// ============================================================
__global__ void __launch_bounds__(256)
readout_kernel(float* __restrict__ xy, float* __restrict__ dxy,
               const float* __restrict__ b2, float* __restrict__ out, int step)
{
    int i = blockIdx.x * blockDim.x + threadIdx.x;
    if (i < B_) {
        float4 d  = reinterpret_cast<float4*>(dxy)[i];
        float4 xv = reinterpret_cast<float4*>(xy)[i];
        xv.x += d.x + b2[0];
        xv.y += d.y + b2[1];
        xv.z += d.z + b2[2];
        xv.w += d.w + b2[3];
        reinterpret_cast<float4*>(xy)[i] = xv;
        reinterpret_cast<float4*>(out)[(size_t)i * HOR_ + step] = xv;
        reinterpret_cast<float4*>(dxy)[i] = make_float4(0.f, 0.f, 0.f, 0.f);
    }
}

// ============================================================
// Launch
// ============================================================
extern "C" void kernel_launch(void* const* d_in, const int* in_sizes, int n_in,
                              void* d_out, int out_size)
{
    const float* pv   = (const float*)d_in[0];
    const float* ptf  = (const float*)d_in[1];
    const float* w_ih = (const float*)d_in[2];
    const float* w_hh = (const float*)d_in[3];
    const float* b_ih = (const float*)d_in[4];
    const float* b_hh = (const float*)d_in[5];
    const float* w_fc = (const float*)d_in[6];
    const float* b_fc = (const float*)d_in[7];
    const float* w1   = (const float*)d_in[8];
    const float* b1   = (const float*)d_in[9];
    const float* w2   = (const float*)d_in[10];
    const float* b2   = (const float*)d_in[11];
    float* out = (float*)d_out;

    float *h1, *hx, *xy, *dxy;
    __half *h1h, *h2h, *hxh, *hxRh, *ptfh, *whhh, *wfch, *w1h;
    cudaGetSymbolAddress((void**)&h1,   g_h1);
    cudaGetSymbolAddress((void**)&hx,   g_hx);
    cudaGetSymbolAddress((void**)&xy,   g_xy);
    cudaGetSymbolAddress((void**)&dxy,  g_dxy);
    cudaGetSymbolAddress((void**)&h1h,  g_h1h);
    cudaGetSymbolAddress((void**)&h2h,  g_h2h);
    cudaGetSymbolAddress((void**)&hxh,  g_hxh);
    cudaGetSymbolAddress((void**)&hxRh, g_hxRh);
    cudaGetSymbolAddress((void**)&ptfh, g_ptfh);
    cudaGetSymbolAddress((void**)&whhh, g_whhh);
    cudaGetSymbolAddress((void**)&wfch, g_wfch);
    cudaGetSymbolAddress((void**)&w1h,  g_w1h);

    cudaFuncSetAttribute(hh_fused,
        cudaFuncAttributeMaxDynamicSharedMemorySize, HH_SMEM_BYTES);
    cudaFuncSetAttribute(gemm_fc,
        cudaFuncAttributeMaxDynamicSharedMemorySize, GC3_SMEM_BYTES);
    cudaFuncSetAttribute(gemm_mlp,
        cudaFuncAttributeMaxDynamicSharedMemorySize, GC2_SMEM_BYTES);

    // ---- prep ----
    cvt_kernel<<<(3 * H_ * H_ / 4 + 255) / 256, 256>>>(w_hh, whhh, 3 * H_ * H_ / 4);
    cvt_kernel<<<(H_ * 2 * H_ / 4 + 255) / 256, 256>>>(w_fc, wfch, H_ * 2 * H_ / 4);
    cvt_kernel<<<(FF_ * H_ / 4 + 255) / 256, 256>>>(w1, w1h, FF_ * H_ / 4);
    cvt_kernel<<<(B_ * H_ / 4 + 255) / 256, 256>>>(ptf, ptfh, B_ * H_ / 4);
    zero_kernel<<<(B_ * OUT_ + 255) / 256, 256>>>(xy, B_ * OUT_);
    zero_kernel<<<(B_ * OUT_ + 255) / 256, 256>>>(dxy, B_ * OUT_);

    const dim3 gridHH(B_ / 128, H_ / 64);      // (128, 8)
    const dim3 gridFC(B_ / 128, H_ / 128);     // (128, 4)
    const dim3 gridM1(B_ / 128, FF_ / 128);    // (128, 16)

    for (int step = 0; step < HOR_; step++) {
        const __half* hxin_h = (step == 0) ? ptfh : hxh;
        const float*  hxin_f = (step == 0) ? ptf  : hx;

        hh_fused<<<gridHH, 256, HH_SMEM_BYTES>>>(
            hxin_h, whhh, hxin_f, xy, OUT_, w_ih, b_ih, b_hh, h1, h1h);

        hh_fused<<<gridHH, 256, HH_SMEM_BYTES>>>(
            h1h, whhh, h1, pv + step * OUT_, HOR_ * OUT_, w_ih, b_ih, b_hh,
            nullptr, h2h);

        gemm_fc<<<gridFC, 256, GC3_SMEM_BYTES>>>(h1h, h2h, wfch, b_fc,
                                                 hx, hxh, hxRh);

        gemm_mlp<<<gridM1, 256, GC2_SMEM_BYTES>>>(hxRh, w1h, b1, w2, dxy);

        readout_kernel<<<B_ / 256, 256>>>(xy, dxy, b2, out, step);
    }
}

// round 14
// speedup vs baseline: 1.1783x; 1.0251x over previous
#include <cuda_runtime.h>
#include <cuda_fp16.h>
#include <math.h>
#include <stdint.h>

#define B_   16384
#define H_   512
#define FF_  2048
#define OUT_ 4
#define HOR_ 5

// ---- scratch (device globals; no allocation) ----
__device__ float  g_h1[B_ * H_];
__device__ float  g_hx[B_ * H_];
__device__ float  g_xy[B_ * OUT_];
__device__ float  g_dxy[B_ * OUT_];
// fp16 copies (GEMM operands)
__device__ __half g_h1h[B_ * H_];
__device__ __half g_h2h[B_ * H_];
__device__ __half g_hxh[B_ * H_];
__device__ __half g_hxRh[B_ * H_];
__device__ __half g_ptfh[B_ * H_];
__device__ __half g_whhh[3 * H_ * H_];
__device__ __half g_wfch[H_ * 2 * H_];
__device__ __half g_w1h[FF_ * H_];

// ============================================================
// helpers
// ============================================================
__device__ __forceinline__ void mma_f16(float c[4], const uint32_t a[4],
                                        const uint32_t b[2]) {
    asm volatile(
        "mma.sync.aligned.m16n8k16.row.col.f32.f16.f16.f32 "
        "{%0,%1,%2,%3}, {%4,%5,%6,%7}, {%8,%9}, {%0,%1,%2,%3};"
        : "+f"(c[0]), "+f"(c[1]), "+f"(c[2]), "+f"(c[3])
        : "r"(a[0]), "r"(a[1]), "r"(a[2]), "r"(a[3]),
          "r"(b[0]), "r"(b[1]));
}

__device__ __forceinline__ void ldsm_x4(uint32_t r[4], uint32_t saddr) {
    asm volatile("ldmatrix.sync.aligned.m8n8.x4.shared.b16 {%0,%1,%2,%3}, [%4];"
                 : "=r"(r[0]), "=r"(r[1]), "=r"(r[2]), "=r"(r[3])
                 : "r"(saddr));
}

__device__ __forceinline__ void cp16(void* smem_ptr, const void* gsrc) {
    uint32_t a = (uint32_t)__cvta_generic_to_shared(smem_ptr);
    asm volatile("cp.async.cg.shared.global [%0], [%1], 16;"
                 :: "r"(a), "l"(gsrc));
}

#define CP_COMMIT() asm volatile("cp.async.commit_group;" ::: "memory")
#define CP_WAIT(n)  asm volatile("cp.async.wait_group %0;" :: "n"(n) : "memory")

__device__ __forceinline__ float fast_sigmoid(float x) {
    return __fdividef(1.f, 1.f + __expf(-x));
}
__device__ __forceinline__ float fast_tanh(float x) {
    float e = __expf(-2.f * x);
    return __fdividef(1.f - e, 1.f + e);
}

// ============================================================
// prep kernels
// ============================================================
__global__ void cvt_kernel(const float* __restrict__ src,
                           __half* __restrict__ dst, int n4) {
    int i = blockIdx.x * blockDim.x + threadIdx.x;
    if (i < n4) {
        float4 v = reinterpret_cast<const float4*>(src)[i];
        reinterpret_cast<__half2*>(dst)[i * 2]     = __floats2half2_rn(v.x, v.y);
        reinterpret_cast<__half2*>(dst)[i * 2 + 1] = __floats2half2_rn(v.z, v.w);
    }
}

__global__ void zero_kernel(float* __restrict__ p, int n) {
    int i = blockIdx.x * blockDim.x + threadIdx.x;
    if (i < n) p[i] = 0.f;
}

#define SMSH 40   // smem row pitch in halves: 32 + 8 pad (80B)

// ============================================================
// Gate-fused HH GEMM (fp16, ldmatrix, 3-stage cp.async, 2 CTAs/SM).
// ============================================================
#define HH_STAGE_H (320 * SMSH)
#define HH_SMEM_BYTES (3u * HH_STAGE_H * 2u)

__global__ void __launch_bounds__(256, 2)
hh_fused(const __half* __restrict__ Ah, const __half* __restrict__ Whh,
         const float* __restrict__ hf, const float* __restrict__ x, int xstride,
         const float* __restrict__ w_ih, const float* __restrict__ b_ih,
         const float* __restrict__ b_hh,
         float* __restrict__ hout, __half* __restrict__ houth)
{
    extern __shared__ __half smh[];

    const int tid  = threadIdx.x;
    const int warp = tid >> 5;
    const int lane = tid & 31;
    const int gid  = lane >> 2;
    const int tig  = lane & 3;
    const int wm   = warp >> 1;
    const int wn   = warp & 1;
    const int bm   = blockIdx.x * 128;
    const int bn   = blockIdx.y * 64;

    const uint32_t sbase = (uint32_t)__cvta_generic_to_shared(smh);
    const int la_row = ((lane & 8) ? 8 : 0) + (lane & 7);
    const int la_k   = (lane & 16) ? 8 : 0;
    const int lb_n   = ((lane & 16) ? 8 : 0) + (lane & 7);
    const int lb_k   = (lane & 8) ? 8 : 0;

    float acc[3][2][4][4];
#pragma unroll
    for (int g = 0; g < 3; g++)
#pragma unroll
        for (int i = 0; i < 2; i++)
#pragma unroll
            for (int j = 0; j < 4; j++)
#pragma unroll
                for (int r = 0; r < 4; r++) acc[g][i][j][r] = 0.f;

    auto issue = [&](int t) {
        const int s  = t % 3;
        const int k0 = t * 32;
        __half* base = smh + s * HH_STAGE_H;
#pragma unroll
        for (int it = 0; it < 2; it++) {
            int lin = tid + it * 256;
            int row = lin >> 2, j = lin & 3;
            cp16(&base[row * SMSH + j * 8],
                 &Ah[(size_t)(bm + row) * 512 + k0 + j * 8]);
        }
#pragma unroll
        for (int it = 0; it < 3; it++) {
            int lin = tid + it * 256;
            int row = lin >> 2, j = lin & 3;
            int g = row >> 6, lr = row & 63;
            cp16(&base[(128 + row) * SMSH + j * 8],
                 &Whh[(size_t)(g * 512 + bn + lr) * 512 + k0 + j * 8]);
        }
        CP_COMMIT();
    };

    issue(0); issue(1); issue(2);

    for (int t = 0; t < 16; t++) {
        const int rem = 15 - t;
        if (rem >= 2)      CP_WAIT(2);
        else if (rem == 1) CP_WAIT(1);
        else               CP_WAIT(0);
        __syncthreads();

        const uint32_t st = sbase + (uint32_t)((t % 3) * HH_STAGE_H) * 2u;

#pragma unroll
        for (int kk = 0; kk < 2; kk++) {
            uint32_t afr[2][4];
#pragma unroll
            for (int i = 0; i < 2; i++)
                ldsm_x4(afr[i], st + (uint32_t)(
                    (wm * 32 + i * 16 + la_row) * SMSH + kk * 16 + la_k) * 2u);
#pragma unroll
            for (int g = 0; g < 3; g++) {
                uint32_t bfr[4][2];
#pragma unroll
                for (int jp = 0; jp < 2; jp++) {
                    uint32_t r[4];
                    ldsm_x4(r, st + (uint32_t)(
                        (128 + g * 64 + wn * 32 + jp * 16 + lb_n) * SMSH
                        + kk * 16 + lb_k) * 2u);
                    bfr[jp * 2][0]     = r[0]; bfr[jp * 2][1]     = r[1];
                    bfr[jp * 2 + 1][0] = r[2]; bfr[jp * 2 + 1][1] = r[3];
                }
#pragma unroll
                for (int i = 0; i < 2; i++)
#pragma unroll
                    for (int j = 0; j < 4; j++)
                        mma_f16(acc[g][i][j], afr[i], bfr[j]);
            }
        }
        __syncthreads();
        if (t + 3 < 16) issue(t + 3);
    }

    // ---- fused gate epilogue ----
#pragma unroll
    for (int i = 0; i < 2; i++) {
        const int r0 = bm + wm * 32 + i * 16 + gid;
        const int r1 = r0 + 8;
        const float4 xv0 = *reinterpret_cast<const float4*>(&x[(size_t)r0 * xstride]);
        const float4 xv1 = *reinterpret_cast<const float4*>(&x[(size_t)r1 * xstride]);
#pragma unroll
        for (int j = 0; j < 4; j++) {
            const int col = bn + wn * 32 + j * 8 + tig * 2;
            const float2 hp0 = *reinterpret_cast<const float2*>(&hf[(size_t)r0 * 512 + col]);
            const float2 hp1 = *reinterpret_cast<const float2*>(&hf[(size_t)r1 * 512 + col]);
            float res[2][2];
#pragma unroll
            for (int c = 0; c < 2; c++) {
                const int cc = col + c;
                const float4 wr  = *reinterpret_cast<const float4*>(&w_ih[(size_t)cc * 4]);
                const float4 wz  = *reinterpret_cast<const float4*>(&w_ih[(size_t)(cc + 512) * 4]);
                const float4 wnn = *reinterpret_cast<const float4*>(&w_ih[(size_t)(cc + 1024) * 4]);
                const float bir = b_ih[cc], biz = b_ih[cc + 512], bin = b_ih[cc + 1024];
                const float bhr = b_hh[cc], bhz = b_hh[cc + 512], bhn = b_hh[cc + 1024];
#pragma unroll
                for (int rr = 0; rr < 2; rr++) {
                    const float4 xv = rr ? xv1 : xv0;
                    float gir = bir + xv.x*wr.x + xv.y*wr.y + xv.z*wr.z + xv.w*wr.w;
                    float giz = biz + xv.x*wz.x + xv.y*wz.y + xv.z*wz.z + xv.w*wz.w;
                    float gin = bin + xv.x*wnn.x + xv.y*wnn.y + xv.z*wnn.z + xv.w*wnn.w;
                    float ghr = acc[0][i][j][rr * 2 + c] + bhr;
                    float ghz = acc[1][i][j][rr * 2 + c] + bhz;
                    float ghn = acc[2][i][j][rr * 2 + c] + bhn;
                    float rg = fast_sigmoid(gir + ghr);
                    float zg = fast_sigmoid(giz + ghz);
                    float ng = fast_tanh(gin + rg * ghn);
                    float hprev = rr ? (c ? hp1.y : hp1.x) : (c ? hp0.y : hp0.x);
                    res[rr][c] = (1.f - zg) * ng + zg * hprev;
                }
            }
            if (hout) {
                *reinterpret_cast<float2*>(&hout[(size_t)r0 * 512 + col])
                    = make_float2(res[0][0], res[0][1]);
                *reinterpret_cast<float2*>(&hout[(size_t)r1 * 512 + col])
                    = make_float2(res[1][0], res[1][1]);
            }
            *reinterpret_cast<__half2*>(&houth[(size_t)r0 * 512 + col])
                = __floats2half2_rn(res[0][0], res[0][1]);
            *reinterpret_cast<__half2*>(&houth[(size_t)r1 * 512 + col])
                = __floats2half2_rn(res[1][0], res[1][1]);
        }
    }
}

// ============================================================
// fc GEMM (3-stage): hx = concat(h1h,h2h) @ wfch^T + b_fc
// TRIPLE write: hx fp32, hxh fp16, hxRh relu fp16.
// ============================================================
#define TILE_H (128 * SMSH)
#define GC3_SMEM_BYTES (6u * TILE_H * 2u)

__global__ void __launch_bounds__(256, 2)
gemm_fc(const __half* __restrict__ A, const __half* __restrict__ A2,
        const __half* __restrict__ W, const float* __restrict__ bias,
        float* __restrict__ C, __half* __restrict__ Ch, __half* __restrict__ Chr)
{
    extern __shared__ __half smh[];
    const int K = 1024, N = 512;

    const int tid  = threadIdx.x;
    const int warp = tid >> 5;
    const int lane = tid & 31;
    const int gid  = lane >> 2;
    const int tig  = lane & 3;
    const int wm   = warp >> 1;
    const int wn   = warp & 1;
    const int bm   = blockIdx.x * 128;
    const int bn   = blockIdx.y * 128;

    const uint32_t sbase = (uint32_t)__cvta_generic_to_shared(smh);
    const int la_row = ((lane & 8) ? 8 : 0) + (lane & 7);
    const int la_k   = (lane & 16) ? 8 : 0;
    const int lb_n   = ((lane & 16) ? 8 : 0) + (lane & 7);
    const int lb_k   = (lane & 8) ? 8 : 0;

    float acc[2][8][4];
#pragma unroll
    for (int i = 0; i < 2; i++)
#pragma unroll
        for (int j = 0; j < 8; j++)
#pragma unroll
            for (int r = 0; r < 4; r++) acc[i][j][r] = 0.f;

    auto issue_tile = [&](int t) {
        const int s  = t % 3;
        const int k0 = t * 32;
        __half* sAh = smh + s * TILE_H;
        __half* sWh = smh + (3 + s) * TILE_H;
#pragma unroll
        for (int it = 0; it < 2; it++) {
            int lin = tid + it * 256;
            int row = lin >> 2, j = lin & 3;
            cp16(&sWh[row * SMSH + j * 8], &W[(size_t)(bn + row) * K + k0 + j * 8]);
            const __half* asrc = (k0 < 512)
                ? &A [(size_t)(bm + row) * 512 + k0 + j * 8]
                : &A2[(size_t)(bm + row) * 512 + (k0 - 512) + j * 8];
            cp16(&sAh[row * SMSH + j * 8], asrc);
        }
        CP_COMMIT();
    };

    const int T = K >> 5;
    issue_tile(0); issue_tile(1); issue_tile(2);

    for (int t = 0; t < T; t++) {
        const int rem = T - 1 - t;
        if (rem >= 2)      CP_WAIT(2);
        else if (rem == 1) CP_WAIT(1);
        else               CP_WAIT(0);
        __syncthreads();

        const uint32_t stA = sbase + (uint32_t)((t % 3) * TILE_H) * 2u;
        const uint32_t stW = sbase + (uint32_t)((3 + t % 3) * TILE_H) * 2u;

#pragma unroll
        for (int kk = 0; kk < 2; kk++) {
            uint32_t afr[2][4];
#pragma unroll
            for (int i = 0; i < 2; i++)
                ldsm_x4(afr[i], stA + (uint32_t)(
                    (wm * 32 + i * 16 + la_row) * SMSH + kk * 16 + la_k) * 2u);
            uint32_t bfr[8][2];
#pragma unroll
            for (int jp = 0; jp < 4; jp++) {
                uint32_t r[4];
                ldsm_x4(r, stW + (uint32_t)(
                    (wn * 64 + jp * 16 + lb_n) * SMSH + kk * 16 + lb_k) * 2u);
                bfr[jp * 2][0]     = r[0]; bfr[jp * 2][1]     = r[1];
                bfr[jp * 2 + 1][0] = r[2]; bfr[jp * 2 + 1][1] = r[3];
            }
#pragma unroll
            for (int i = 0; i < 2; i++)
#pragma unroll
                for (int j = 0; j < 8; j++)
                    mma_f16(acc[i][j], afr[i], bfr[j]);
        }
        __syncthreads();
        if (t + 3 < T) issue_tile(t + 3);
    }

#pragma unroll
    for (int i = 0; i < 2; i++) {
        int row0 = bm + wm * 32 + i * 16 + gid;
#pragma unroll
        for (int j = 0; j < 8; j++) {
            int col = bn + wn * 64 + j * 8 + tig * 2;
            float b0 = bias[col], b1v = bias[col + 1];
            float v0 = acc[i][j][0] + b0;
            float v1 = acc[i][j][1] + b1v;
            float v2 = acc[i][j][2] + b0;
            float v3 = acc[i][j][3] + b1v;
            *reinterpret_cast<float2*>(&C[(size_t)row0 * N + col]) = make_float2(v0, v1);
            *reinterpret_cast<float2*>(&C[(size_t)(row0 + 8) * N + col]) = make_float2(v2, v3);
            *reinterpret_cast<__half2*>(&Ch[(size_t)row0 * N + col])
                = __floats2half2_rn(v0, v1);
            *reinterpret_cast<__half2*>(&Ch[(size_t)(row0 + 8) * N + col])
                = __floats2half2_rn(v2, v3);
            *reinterpret_cast<__half2*>(&Chr[(size_t)row0 * N + col])
                = __floats2half2_rn(fmaxf(v0, 0.f), fmaxf(v1, 0.f));
            *reinterpret_cast<__half2*>(&Chr[(size_t)(row0 + 8) * N + col])
                = __floats2half2_rn(fmaxf(v2, 0.f), fmaxf(v3, 0.f));
        }
    }
}

// ============================================================
// MLP GEMM fused with w2 contraction, 2 n-tiles per CTA, 3-stage.
// grid (B/128, FF/256).  Flat 32-tile loop: tt -> (nt = tt>>4, k = tt&15).
// a1 = relu(A @ w1h^T + b1);  dxy += a1 @ w2_slice^T (atomics).
// ============================================================
__global__ void __launch_bounds__(256, 2)
gemm_mlp(const __half* __restrict__ A, const __half* __restrict__ W,
         const float* __restrict__ b1g, const float* __restrict__ w2,
         float* __restrict__ dxy)
{
    extern __shared__ __half smh[];
    __shared__ float sw2[4][256];
    __shared__ float sdxy[128][4];
    const int K = 512;

    const int tid  = threadIdx.x;
    const int warp = tid >> 5;
    const int lane = tid & 31;
    const int gid  = lane >> 2;
    const int tig  = lane & 3;
    const int wm   = warp >> 1;
    const int wn   = warp & 1;
    const int bm   = blockIdx.x * 128;
    const int bn   = blockIdx.y * 256;

    const uint32_t sbase = (uint32_t)__cvta_generic_to_shared(smh);
    const int la_row = ((lane & 8) ? 8 : 0) + (lane & 7);
    const int la_k   = (lane & 16) ? 8 : 0;
    const int lb_n   = ((lane & 16) ? 8 : 0) + (lane & 7);
    const int lb_k   = (lane & 8) ? 8 : 0;

    for (int i = tid; i < 4 * 256; i += 256)
        sw2[i >> 8][i & 255] = w2[(size_t)(i >> 8) * 2048 + bn + (i & 255)];
    for (int i = tid; i < 512; i += 256)
        reinterpret_cast<float*>(sdxy)[i] = 0.f;

    auto issue_tile = [&](int tt) {
        const int s  = tt % 3;
        const int nt = tt >> 4;
        const int k0 = (tt & 15) * 32;
        __half* sAh = smh + s * TILE_H;
        __half* sWh = smh + (3 + s) * TILE_H;
#pragma unroll
        for (int it = 0; it < 2; it++) {
            int lin = tid + it * 256;
            int row = lin >> 2, j = lin & 3;
            cp16(&sWh[row * SMSH + j * 8],
                 &W[(size_t)(bn + nt * 128 + row) * K + k0 + j * 8]);
            cp16(&sAh[row * SMSH + j * 8],
                 &A[(size_t)(bm + row) * K + k0 + j * 8]);
        }
        CP_COMMIT();
    };

    issue_tile(0); issue_tile(1); issue_tile(2);

    float p[2][2][4];
#pragma unroll
    for (int i = 0; i < 2; i++)
#pragma unroll
        for (int rr = 0; rr < 2; rr++)
#pragma unroll
            for (int o = 0; o < 4; o++) p[i][rr][o] = 0.f;

    float acc[2][8][4];

    for (int tt = 0; tt < 32; tt++) {
        const int rem = 31 - tt;
        if (rem >= 2)      CP_WAIT(2);
        else if (rem == 1) CP_WAIT(1);
        else               CP_WAIT(0);
        __syncthreads();

        if ((tt & 15) == 0) {
#pragma unroll
            for (int i = 0; i < 2; i++)
#pragma unroll
                for (int j = 0; j < 8; j++)
#pragma unroll
                    for (int r = 0; r < 4; r++) acc[i][j][r] = 0.f;
        }

        const uint32_t stA = sbase + (uint32_t)((tt % 3) * TILE_H) * 2u;
        const uint32_t stW = sbase + (uint32_t)((3 + tt % 3) * TILE_H) * 2u;

#pragma unroll
        for (int kk = 0; kk < 2; kk++) {
            uint32_t afr[2][4];
#pragma unroll
            for (int i = 0; i < 2; i++)
                ldsm_x4(afr[i], stA + (uint32_t)(
                    (wm * 32 + i * 16 + la_row) * SMSH + kk * 16 + la_k) * 2u);
            uint32_t bfr[8][2];
#pragma unroll
            for (int jp = 0; jp < 4; jp++) {
                uint32_t r[4];
                ldsm_x4(r, stW + (uint32_t)(
                    (wn * 64 + jp * 16 + lb_n) * SMSH + kk * 16 + lb_k) * 2u);
                bfr[jp * 2][0]     = r[0]; bfr[jp * 2][1]     = r[1];
                bfr[jp * 2 + 1][0] = r[2]; bfr[jp * 2 + 1][1] = r[3];
            }
#pragma unroll
            for (int i = 0; i < 2; i++)
#pragma unroll
                for (int j = 0; j < 8; j++)
                    mma_f16(acc[i][j], afr[i], bfr[j]);
        }
        __syncthreads();
        if (tt + 3 < 32) issue_tile(tt + 3);

        if ((tt & 15) == 15) {
            const int nb = (tt >> 4) * 128;
#pragma unroll
            for (int i = 0; i < 2; i++)
#pragma unroll
                for (int j = 0; j < 8; j++) {
                    const int lc = wn * 64 + j * 8 + tig * 2;
                    const float bb0 = b1g[bn + nb + lc];
                    const float bb1 = b1g[bn + nb + lc + 1];
                    const float a00 = fmaxf(acc[i][j][0] + bb0, 0.f);
                    const float a01 = fmaxf(acc[i][j][1] + bb1, 0.f);
                    const float a10 = fmaxf(acc[i][j][2] + bb0, 0.f);
                    const float a11 = fmaxf(acc[i][j][3] + bb1, 0.f);
#pragma unroll
                    for (int o = 0; o < 4; o++) {
                        const float w0 = sw2[o][nb + lc];
                        const float w1 = sw2[o][nb + lc + 1];
                        p[i][0][o] += a00 * w0 + a01 * w1;
                        p[i][1][o] += a10 * w0 + a11 * w1;
                    }
                }
        }
    }

    // ---- reduce and atomically accumulate ----
#pragma unroll
    for (int i = 0; i < 2; i++)
#pragma unroll
        for (int rr = 0; rr < 2; rr++)
#pragma unroll
            for (int o = 0; o < 4; o++) {
                float v = p[i][rr][o];
                v += __shfl_xor_sync(0xFFFFFFFFu, v, 1);
                v += __shfl_xor_sync(0xFFFFFFFFu, v, 2);
                p[i][rr][o] = v;
            }
    if (tig == 0) {
#pragma unroll
        for (int i = 0; i < 2; i++)
#pragma unroll
            for (int rr = 0; rr < 2; rr++) {
                const int row = wm * 32 + i * 16 + rr * 8 + gid;
#pragma unroll
                for (int o = 0; o < 4; o++)
                    atomicAdd(&sdxy[row][o], p[i][rr][o]);
            }
    }
    __syncthreads();
    for (int i = tid; i < 512; i += 256) {
        const int row = i >> 2, o = i & 3;
        atomicAdd(&dxy[(size_t)(bm + row) * 4 + o], sdxy[row][o]);
    }
}

// ============================================================
// readout: xy += dxy + b2; out[:, step] = xy; dxy = 0
// ============================================================
__global__ void __launch_bounds__(256)
readout_kernel(float* __restrict__ xy, float* __restrict__ dxy,
               const float* __restrict__ b2, float* __restrict__ out, int step)
{
    int i = blockIdx.x * blockDim.x + threadIdx.x;
    if (i < B_) {
        float4 d  = reinterpret_cast<float4*>(dxy)[i];
        float4 xv = reinterpret_cast<float4*>(xy)[i];
        xv.x += d.x + b2[0];
        xv.y += d.y + b2[1];
        xv.z += d.z + b2[2];
        xv.w += d.w + b2[3];
        reinterpret_cast<float4*>(xy)[i] = xv;
        reinterpret_cast<float4*>(out)[(size_t)i * HOR_ + step] = xv;
        reinterpret_cast<float4*>(dxy)[i] = make_float4(0.f, 0.f, 0.f, 0.f);
    }
}

// ============================================================
// Launch
// ============================================================
extern "C" void kernel_launch(void* const* d_in, const int* in_sizes, int n_in,
                              void* d_out, int out_size)
{
    const float* pv   = (const float*)d_in[0];
    const float* ptf  = (const float*)d_in[1];
    const float* w_ih = (const float*)d_in[2];
    const float* w_hh = (const float*)d_in[3];
    const float* b_ih = (const float*)d_in[4];
    const float* b_hh = (const float*)d_in[5];
    const float* w_fc = (const float*)d_in[6];
    const float* b_fc = (const float*)d_in[7];
    const float* w1   = (const float*)d_in[8];
    const float* b1   = (const float*)d_in[9];
    const float* w2   = (const float*)d_in[10];
    const float* b2   = (const float*)d_in[11];
    float* out = (float*)d_out;

    float *h1, *hx, *xy, *dxy;
    __half *h1h, *h2h, *hxh, *hxRh, *ptfh, *whhh, *wfch, *w1h;
    cudaGetSymbolAddress((void**)&h1,   g_h1);
    cudaGetSymbolAddress((void**)&hx,   g_hx);
    cudaGetSymbolAddress((void**)&xy,   g_xy);
    cudaGetSymbolAddress((void**)&dxy,  g_dxy);
    cudaGetSymbolAddress((void**)&h1h,  g_h1h);
    cudaGetSymbolAddress((void**)&h2h,  g_h2h);
    cudaGetSymbolAddress((void**)&hxh,  g_hxh);
    cudaGetSymbolAddress((void**)&hxRh, g_hxRh);
    cudaGetSymbolAddress((void**)&ptfh, g_ptfh);
    cudaGetSymbolAddress((void**)&whhh, g_whhh);
    cudaGetSymbolAddress((void**)&wfch, g_wfch);
    cudaGetSymbolAddress((void**)&w1h,  g_w1h);

    cudaFuncSetAttribute(hh_fused,
        cudaFuncAttributeMaxDynamicSharedMemorySize, HH_SMEM_BYTES);
    cudaFuncSetAttribute(gemm_fc,
        cudaFuncAttributeMaxDynamicSharedMemorySize, GC3_SMEM_BYTES);
    cudaFuncSetAttribute(gemm_mlp,
        cudaFuncAttributeMaxDynamicSharedMemorySize, GC3_SMEM_BYTES);

    // ---- prep ----
    cvt_kernel<<<(3 * H_ * H_ / 4 + 255) / 256, 256>>>(w_hh, whhh, 3 * H_ * H_ / 4);
    cvt_kernel<<<(H_ * 2 * H_ / 4 + 255) / 256, 256>>>(w_fc, wfch, H_ * 2 * H_ / 4);
    cvt_kernel<<<(FF_ * H_ / 4 + 255) / 256, 256>>>(w1, w1h, FF_ * H_ / 4);
    cvt_kernel<<<(B_ * H_ / 4 + 255) / 256, 256>>>(ptf, ptfh, B_ * H_ / 4);
    zero_kernel<<<(B_ * OUT_ + 255) / 256, 256>>>(xy, B_ * OUT_);
    zero_kernel<<<(B_ * OUT_ + 255) / 256, 256>>>(dxy, B_ * OUT_);

    const dim3 gridHH(B_ / 128, H_ / 64);      // (128, 8)
    const dim3 gridFC(B_ / 128, H_ / 128);     // (128, 4)
    const dim3 gridM1(B_ / 128, FF_ / 256);    // (128, 8)

    for (int step = 0; step < HOR_; step++) {
        const __half* hxin_h = (step == 0) ? ptfh : hxh;
        const float*  hxin_f = (step == 0) ? ptf  : hx;

        hh_fused<<<gridHH, 256, HH_SMEM_BYTES>>>(
            hxin_h, whhh, hxin_f, xy, OUT_, w_ih, b_ih, b_hh, h1, h1h);

        hh_fused<<<gridHH, 256, HH_SMEM_BYTES>>>(
            h1h, whhh, h1, pv + step * OUT_, HOR_ * OUT_, w_ih, b_ih, b_hh,
            nullptr, h2h);

        gemm_fc<<<gridFC, 256, GC3_SMEM_BYTES>>>(h1h, h2h, wfch, b_fc,
                                                 hx, hxh, hxRh);

        gemm_mlp<<<gridM1, 256, GC3_SMEM_BYTES>>>(hxRh, w1h, b1, w2, dxy);

        readout_kernel<<<B_ / 256, 256>>>(xy, dxy, b2, out, step);
    }
}

// round 16
// speedup vs baseline: 1.2328x; 1.0463x over previous
#include <cuda_runtime.h>
#include <cuda_fp16.h>
#include <math.h>
#include <stdint.h>

#define B_   16384
#define H_   512
#define FF_  2048
#define OUT_ 4
#define HOR_ 5

// ---- scratch (device globals; no allocation) ----
__device__ float  g_h1[B_ * H_];
__device__ float  g_hx[B_ * H_];
__device__ float  g_xy[B_ * OUT_];
__device__ float  g_dxy[B_ * OUT_];
// fp16 copies (GEMM operands)
__device__ __half g_h1h[B_ * H_];
__device__ __half g_h2h[B_ * H_];
__device__ __half g_hxh[B_ * H_];
__device__ __half g_hxRh[B_ * H_];
__device__ __half g_ptfh[B_ * H_];
__device__ __half g_whhh[3 * H_ * H_];
__device__ __half g_wfch[H_ * 2 * H_];
__device__ __half g_w1h[FF_ * H_];

// ============================================================
// helpers
// ============================================================
__device__ __forceinline__ void mma_f16(float c[4], const uint32_t a[4],
                                        const uint32_t b[2]) {
    asm volatile(
        "mma.sync.aligned.m16n8k16.row.col.f32.f16.f16.f32 "
        "{%0,%1,%2,%3}, {%4,%5,%6,%7}, {%8,%9}, {%0,%1,%2,%3};"
        : "+f"(c[0]), "+f"(c[1]), "+f"(c[2]), "+f"(c[3])
        : "r"(a[0]), "r"(a[1]), "r"(a[2]), "r"(a[3]),
          "r"(b[0]), "r"(b[1]));
}

__device__ __forceinline__ void ldsm_x4(uint32_t r[4], uint32_t saddr) {
    asm volatile("ldmatrix.sync.aligned.m8n8.x4.shared.b16 {%0,%1,%2,%3}, [%4];"
                 : "=r"(r[0]), "=r"(r[1]), "=r"(r[2]), "=r"(r[3])
                 : "r"(saddr));
}

__device__ __forceinline__ void cp16(void* smem_ptr, const void* gsrc) {
    uint32_t a = (uint32_t)__cvta_generic_to_shared(smem_ptr);
    asm volatile("cp.async.cg.shared.global [%0], [%1], 16;"
                 :: "r"(a), "l"(gsrc));
}

#define CP_COMMIT() asm volatile("cp.async.commit_group;" ::: "memory")
#define CP_WAIT(n)  asm volatile("cp.async.wait_group %0;" :: "n"(n) : "memory")

__device__ __forceinline__ float fast_sigmoid(float x) {
    return __fdividef(1.f, 1.f + __expf(-x));
}
__device__ __forceinline__ float fast_tanh(float x) {
    float e = __expf(-2.f * x);
    return __fdividef(1.f - e, 1.f + e);
}

// ============================================================
// prep kernels
// ============================================================
__global__ void cvt_kernel(const float* __restrict__ src,
                           __half* __restrict__ dst, int n4) {
    int i = blockIdx.x * blockDim.x + threadIdx.x;
    if (i < n4) {
        float4 v = reinterpret_cast<const float4*>(src)[i];
        reinterpret_cast<__half2*>(dst)[i * 2]     = __floats2half2_rn(v.x, v.y);
        reinterpret_cast<__half2*>(dst)[i * 2 + 1] = __floats2half2_rn(v.z, v.w);
    }
}

__global__ void zero_kernel(float* __restrict__ p, int n) {
    int i = blockIdx.x * blockDim.x + threadIdx.x;
    if (i < n) p[i] = 0.f;
}

#define SMSH 40   // smem row pitch in halves: 32 + 8 pad (80B)

// ============================================================
// Gate-fused HH GEMM.  3-stage cp.async, SINGLE sync per tile:
//   wait -> sync -> issue(t+2) -> compute(t%3)
// (stage (t+2)%3 == (t-1)%3, whose readers finished before this sync)
// ============================================================
#define HH_STAGE_H (320 * SMSH)
#define HH_SMEM_BYTES (3u * HH_STAGE_H * 2u)

__global__ void __launch_bounds__(256, 2)
hh_fused(const __half* __restrict__ Ah, const __half* __restrict__ Whh,
         const float* __restrict__ hf, const float* __restrict__ x, int xstride,
         const float* __restrict__ w_ih, const float* __restrict__ b_ih,
         const float* __restrict__ b_hh,
         float* __restrict__ hout, __half* __restrict__ houth)
{
    extern __shared__ __half smh[];

    const int tid  = threadIdx.x;
    const int warp = tid >> 5;
    const int lane = tid & 31;
    const int gid  = lane >> 2;
    const int tig  = lane & 3;
    const int wm   = warp >> 1;
    const int wn   = warp & 1;
    const int bm   = blockIdx.x * 128;
    const int bn   = blockIdx.y * 64;

    const uint32_t sbase = (uint32_t)__cvta_generic_to_shared(smh);
    const int la_row = ((lane & 8) ? 8 : 0) + (lane & 7);
    const int la_k   = (lane & 16) ? 8 : 0;
    const int lb_n   = ((lane & 16) ? 8 : 0) + (lane & 7);
    const int lb_k   = (lane & 8) ? 8 : 0;

    float acc[3][2][4][4];
#pragma unroll
    for (int g = 0; g < 3; g++)
#pragma unroll
        for (int i = 0; i < 2; i++)
#pragma unroll
            for (int j = 0; j < 4; j++)
#pragma unroll
                for (int r = 0; r < 4; r++) acc[g][i][j][r] = 0.f;

    auto issue = [&](int t) {
        const int s  = t % 3;
        const int k0 = t * 32;
        __half* base = smh + s * HH_STAGE_H;
#pragma unroll
        for (int it = 0; it < 2; it++) {
            int lin = tid + it * 256;
            int row = lin >> 2, j = lin & 3;
            cp16(&base[row * SMSH + j * 8],
                 &Ah[(size_t)(bm + row) * 512 + k0 + j * 8]);
        }
#pragma unroll
        for (int it = 0; it < 3; it++) {
            int lin = tid + it * 256;
            int row = lin >> 2, j = lin & 3;
            int g = row >> 6, lr = row & 63;
            cp16(&base[(128 + row) * SMSH + j * 8],
                 &Whh[(size_t)(g * 512 + bn + lr) * 512 + k0 + j * 8]);
        }
        CP_COMMIT();
    };

    issue(0); issue(1);

    for (int t = 0; t < 16; t++) {
        const int rem = 15 - t;
        if (rem >= 1) CP_WAIT(1);
        else          CP_WAIT(0);
        __syncthreads();
        if (t + 2 < 16) issue(t + 2);

        const uint32_t st = sbase + (uint32_t)((t % 3) * HH_STAGE_H) * 2u;

#pragma unroll
        for (int kk = 0; kk < 2; kk++) {
            uint32_t afr[2][4];
#pragma unroll
            for (int i = 0; i < 2; i++)
                ldsm_x4(afr[i], st + (uint32_t)(
                    (wm * 32 + i * 16 + la_row) * SMSH + kk * 16 + la_k) * 2u);
#pragma unroll
            for (int g = 0; g < 3; g++) {
                uint32_t bfr[4][2];
#pragma unroll
                for (int jp = 0; jp < 2; jp++) {
                    uint32_t r[4];
                    ldsm_x4(r, st + (uint32_t)(
                        (128 + g * 64 + wn * 32 + jp * 16 + lb_n) * SMSH
                        + kk * 16 + lb_k) * 2u);
                    bfr[jp * 2][0]     = r[0]; bfr[jp * 2][1]     = r[1];
                    bfr[jp * 2 + 1][0] = r[2]; bfr[jp * 2 + 1][1] = r[3];
                }
#pragma unroll
                for (int i = 0; i < 2; i++)
#pragma unroll
                    for (int j = 0; j < 4; j++)
                        mma_f16(acc[g][i][j], afr[i], bfr[j]);
            }
        }
    }

    // ---- fused gate epilogue ----
#pragma unroll
    for (int i = 0; i < 2; i++) {
        const int r0 = bm + wm * 32 + i * 16 + gid;
        const int r1 = r0 + 8;
        const float4 xv0 = *reinterpret_cast<const float4*>(&x[(size_t)r0 * xstride]);
        const float4 xv1 = *reinterpret_cast<const float4*>(&x[(size_t)r1 * xstride]);
#pragma unroll
        for (int j = 0; j < 4; j++) {
            const int col = bn + wn * 32 + j * 8 + tig * 2;
            const float2 hp0 = *reinterpret_cast<const float2*>(&hf[(size_t)r0 * 512 + col]);
            const float2 hp1 = *reinterpret_cast<const float2*>(&hf[(size_t)r1 * 512 + col]);
            float res[2][2];
#pragma unroll
            for (int c = 0; c < 2; c++) {
                const int cc = col + c;
                const float4 wr  = *reinterpret_cast<const float4*>(&w_ih[(size_t)cc * 4]);
                const float4 wz  = *reinterpret_cast<const float4*>(&w_ih[(size_t)(cc + 512) * 4]);
                const float4 wnn = *reinterpret_cast<const float4*>(&w_ih[(size_t)(cc + 1024) * 4]);
                const float bir = b_ih[cc], biz = b_ih[cc + 512], bin = b_ih[cc + 1024];
                const float bhr = b_hh[cc], bhz = b_hh[cc + 512], bhn = b_hh[cc + 1024];
#pragma unroll
                for (int rr = 0; rr < 2; rr++) {
                    const float4 xv = rr ? xv1 : xv0;
                    float gir = bir + xv.x*wr.x + xv.y*wr.y + xv.z*wr.z + xv.w*wr.w;
                    float giz = biz + xv.x*wz.x + xv.y*wz.y + xv.z*wz.z + xv.w*wz.w;
                    float gin = bin + xv.x*wnn.x + xv.y*wnn.y + xv.z*wnn.z + xv.w*wnn.w;
                    float ghr = acc[0][i][j][rr * 2 + c] + bhr;
                    float ghz = acc[1][i][j][rr * 2 + c] + bhz;
                    float ghn = acc[2][i][j][rr * 2 + c] + bhn;
                    float rg = fast_sigmoid(gir + ghr);
                    float zg = fast_sigmoid(giz + ghz);
                    float ng = fast_tanh(gin + rg * ghn);
                    float hprev = rr ? (c ? hp1.y : hp1.x) : (c ? hp0.y : hp0.x);
                    res[rr][c] = (1.f - zg) * ng + zg * hprev;
                }
            }
            if (hout) {
                *reinterpret_cast<float2*>(&hout[(size_t)r0 * 512 + col])
                    = make_float2(res[0][0], res[0][1]);
                *reinterpret_cast<float2*>(&hout[(size_t)r1 * 512 + col])
                    = make_float2(res[1][0], res[1][1]);
            }
            *reinterpret_cast<__half2*>(&houth[(size_t)r0 * 512 + col])
                = __floats2half2_rn(res[0][0], res[0][1]);
            *reinterpret_cast<__half2*>(&houth[(size_t)r1 * 512 + col])
                = __floats2half2_rn(res[1][0], res[1][1]);
        }
    }
}

// ============================================================
// fc GEMM. 4-stage cp.async, single sync per tile:
//   wait -> sync -> issue(t+3) -> compute(t%4)
// TRIPLE write: hx fp32, hxh fp16, hxRh relu fp16.
// ============================================================
#define TILE_H (128 * SMSH)
#define GC4_SMEM_BYTES (8u * TILE_H * 2u)

__global__ void __launch_bounds__(256, 2)
gemm_fc(const __half* __restrict__ A, const __half* __restrict__ A2,
        const __half* __restrict__ W, const float* __restrict__ bias,
        float* __restrict__ C, __half* __restrict__ Ch, __half* __restrict__ Chr)
{
    extern __shared__ __half smh[];
    const int K = 1024, N = 512;

    const int tid  = threadIdx.x;
    const int warp = tid >> 5;
    const int lane = tid & 31;
    const int gid  = lane >> 2;
    const int tig  = lane & 3;
    const int wm   = warp >> 1;
    const int wn   = warp & 1;
    const int bm   = blockIdx.x * 128;
    const int bn   = blockIdx.y * 128;

    const uint32_t sbase = (uint32_t)__cvta_generic_to_shared(smh);
    const int la_row = ((lane & 8) ? 8 : 0) + (lane & 7);
    const int la_k   = (lane & 16) ? 8 : 0;
    const int lb_n   = ((lane & 16) ? 8 : 0) + (lane & 7);
    const int lb_k   = (lane & 8) ? 8 : 0;

    float acc[2][8][4];
#pragma unroll
    for (int i = 0; i < 2; i++)
#pragma unroll
        for (int j = 0; j < 8; j++)
#pragma unroll
            for (int r = 0; r < 4; r++) acc[i][j][r] = 0.f;

    auto issue_tile = [&](int t) {
        const int s  = t & 3;
        const int k0 = t * 32;
        __half* sAh = smh + s * TILE_H;
        __half* sWh = smh + (4 + s) * TILE_H;
#pragma unroll
        for (int it = 0; it < 2; it++) {
            int lin = tid + it * 256;
            int row = lin >> 2, j = lin & 3;
            cp16(&sWh[row * SMSH + j * 8], &W[(size_t)(bn + row) * K + k0 + j * 8]);
            const __half* asrc = (k0 < 512)
                ? &A [(size_t)(bm + row) * 512 + k0 + j * 8]
                : &A2[(size_t)(bm + row) * 512 + (k0 - 512) + j * 8];
            cp16(&sAh[row * SMSH + j * 8], asrc);
        }
        CP_COMMIT();
    };

    const int T = K >> 5;
    issue_tile(0); issue_tile(1); issue_tile(2);

    for (int t = 0; t < T; t++) {
        const int rem = T - 1 - t;
        if (rem >= 2)      CP_WAIT(2);
        else if (rem == 1) CP_WAIT(1);
        else               CP_WAIT(0);
        __syncthreads();
        if (t + 3 < T) issue_tile(t + 3);

        const uint32_t stA = sbase + (uint32_t)((t & 3) * TILE_H) * 2u;
        const uint32_t stW = sbase + (uint32_t)((4 + (t & 3)) * TILE_H) * 2u;

#pragma unroll
        for (int kk = 0; kk < 2; kk++) {
            uint32_t afr[2][4];
#pragma unroll
            for (int i = 0; i < 2; i++)
                ldsm_x4(afr[i], stA + (uint32_t)(
                    (wm * 32 + i * 16 + la_row) * SMSH + kk * 16 + la_k) * 2u);
            uint32_t bfr[8][2];
#pragma unroll
            for (int jp = 0; jp < 4; jp++) {
                uint32_t r[4];
                ldsm_x4(r, stW + (uint32_t)(
                    (wn * 64 + jp * 16 + lb_n) * SMSH + kk * 16 + lb_k) * 2u);
                bfr[jp * 2][0]     = r[0]; bfr[jp * 2][1]     = r[1];
                bfr[jp * 2 + 1][0] = r[2]; bfr[jp * 2 + 1][1] = r[3];
            }
#pragma unroll
            for (int i = 0; i < 2; i++)
#pragma unroll
                for (int j = 0; j < 8; j++)
                    mma_f16(acc[i][j], afr[i], bfr[j]);
        }
    }

#pragma unroll
    for (int i = 0; i < 2; i++) {
        int row0 = bm + wm * 32 + i * 16 + gid;
#pragma unroll
        for (int j = 0; j < 8; j++) {
            int col = bn + wn * 64 + j * 8 + tig * 2;
            float b0 = bias[col], b1v = bias[col + 1];
            float v0 = acc[i][j][0] + b0;
            float v1 = acc[i][j][1] + b1v;
            float v2 = acc[i][j][2] + b0;
            float v3 = acc[i][j][3] + b1v;
            *reinterpret_cast<float2*>(&C[(size_t)row0 * N + col]) = make_float2(v0, v1);
            *reinterpret_cast<float2*>(&C[(size_t)(row0 + 8) * N + col]) = make_float2(v2, v3);
            *reinterpret_cast<__half2*>(&Ch[(size_t)row0 * N + col])
                = __floats2half2_rn(v0, v1);
            *reinterpret_cast<__half2*>(&Ch[(size_t)(row0 + 8) * N + col])
                = __floats2half2_rn(v2, v3);
            *reinterpret_cast<__half2*>(&Chr[(size_t)row0 * N + col])
                = __floats2half2_rn(fmaxf(v0, 0.f), fmaxf(v1, 0.f));
            *reinterpret_cast<__half2*>(&Chr[(size_t)(row0 + 8) * N + col])
                = __floats2half2_rn(fmaxf(v2, 0.f), fmaxf(v3, 0.f));
        }
    }
}

// ============================================================
// MLP GEMM fused with w2 contraction, 2 n-tiles per CTA, 4-stage,
// single sync per tile.  grid (B/128, FF/256).
// ============================================================
__global__ void __launch_bounds__(256, 2)
gemm_mlp(const __half* __restrict__ A, const __half* __restrict__ W,
         const float* __restrict__ b1g, const float* __restrict__ w2,
         float* __restrict__ dxy)
{
    extern __shared__ __half smh[];
    __shared__ float sw2[4][256];
    __shared__ float sdxy[128][4];
    const int K = 512;

    const int tid  = threadIdx.x;
    const int warp = tid >> 5;
    const int lane = tid & 31;
    const int gid  = lane >> 2;
    const int tig  = lane & 3;
    const int wm   = warp >> 1;
    const int wn   = warp & 1;
    const int bm   = blockIdx.x * 128;
    const int bn   = blockIdx.y * 256;

    const uint32_t sbase = (uint32_t)__cvta_generic_to_shared(smh);
    const int la_row = ((lane & 8) ? 8 : 0) + (lane & 7);
    const int la_k   = (lane & 16) ? 8 : 0;
    const int lb_n   = ((lane & 16) ? 8 : 0) + (lane & 7);
    const int lb_k   = (lane & 8) ? 8 : 0;

    for (int i = tid; i < 4 * 256; i += 256)
        sw2[i >> 8][i & 255] = w2[(size_t)(i >> 8) * 2048 + bn + (i & 255)];
    for (int i = tid; i < 512; i += 256)
        reinterpret_cast<float*>(sdxy)[i] = 0.f;

    auto issue_tile = [&](int tt) {
        const int s  = tt & 3;
        const int nt = tt >> 4;
        const int k0 = (tt & 15) * 32;
        __half* sAh = smh + s * TILE_H;
        __half* sWh = smh + (4 + s) * TILE_H;
#pragma unroll
        for (int it = 0; it < 2; it++) {
            int lin = tid + it * 256;
            int row = lin >> 2, j = lin & 3;
            cp16(&sWh[row * SMSH + j * 8],
                 &W[(size_t)(bn + nt * 128 + row) * K + k0 + j * 8]);
            cp16(&sAh[row * SMSH + j * 8],
                 &A[(size_t)(bm + row) * K + k0 + j * 8]);
        }
        CP_COMMIT();
    };

    issue_tile(0); issue_tile(1); issue_tile(2);

    float p[2][2][4];
#pragma unroll
    for (int i = 0; i < 2; i++)
#pragma unroll
        for (int rr = 0; rr < 2; rr++)
#pragma unroll
            for (int o = 0; o < 4; o++) p[i][rr][o] = 0.f;

    float acc[2][8][4];

    for (int tt = 0; tt < 32; tt++) {
        const int rem = 31 - tt;
        if (rem >= 2)      CP_WAIT(2);
        else if (rem == 1) CP_WAIT(1);
        else               CP_WAIT(0);
        __syncthreads();
        if (tt + 3 < 32) issue_tile(tt + 3);

        if ((tt & 15) == 0) {
#pragma unroll
            for (int i = 0; i < 2; i++)
#pragma unroll
                for (int j = 0; j < 8; j++)
#pragma unroll
                    for (int r = 0; r < 4; r++) acc[i][j][r] = 0.f;
        }

        const uint32_t stA = sbase + (uint32_t)((tt & 3) * TILE_H) * 2u;
        const uint32_t stW = sbase + (uint32_t)((4 + (tt & 3)) * TILE_H) * 2u;

#pragma unroll
        for (int kk = 0; kk < 2; kk++) {
            uint32_t afr[2][4];
#pragma unroll
            for (int i = 0; i < 2; i++)
                ldsm_x4(afr[i], stA + (uint32_t)(
                    (wm * 32 + i * 16 + la_row) * SMSH + kk * 16 + la_k) * 2u);
            uint32_t bfr[8][2];
#pragma unroll
            for (int jp = 0; jp < 4; jp++) {
                uint32_t r[4];
                ldsm_x4(r, stW + (uint32_t)(
                    (wn * 64 + jp * 16 + lb_n) * SMSH + kk * 16 + lb_k) * 2u);
                bfr[jp * 2][0]     = r[0]; bfr[jp * 2][1]     = r[1];
                bfr[jp * 2 + 1][0] = r[2]; bfr[jp * 2 + 1][1] = r[3];
            }
#pragma unroll
            for (int i = 0; i < 2; i++)
#pragma unroll
                for (int j = 0; j < 8; j++)
                    mma_f16(acc[i][j], afr[i], bfr[j]);
        }

        if ((tt & 15) == 15) {
            const int nb = (tt >> 4) * 128;
#pragma unroll
            for (int i = 0; i < 2; i++)
#pragma unroll
                for (int j = 0; j < 8; j++) {
                    const int lc = wn * 64 + j * 8 + tig * 2;
                    const float bb0 = b1g[bn + nb + lc];
                    const float bb1 = b1g[bn + nb + lc + 1];
                    const float a00 = fmaxf(acc[i][j][0] + bb0, 0.f);
                    const float a01 = fmaxf(acc[i][j][1] + bb1, 0.f);
                    const float a10 = fmaxf(acc[i][j][2] + bb0, 0.f);
                    const float a11 = fmaxf(acc[i][j][3] + bb1, 0.f);
#pragma unroll
                    for (int o = 0; o < 4; o++) {
                        const float w0 = sw2[o][nb + lc];
                        const float w1 = sw2[o][nb + lc + 1];
                        p[i][0][o] += a00 * w0 + a01 * w1;
                        p[i][1][o] += a10 * w0 + a11 * w1;
                    }
                }
        }
    }

    // ---- reduce and atomically accumulate ----
#pragma unroll
    for (int i = 0; i < 2; i++)
#pragma unroll
        for (int rr = 0; rr < 2; rr++)
#pragma unroll
            for (int o = 0; o < 4; o++) {
                float v = p[i][rr][o];
                v += __shfl_xor_sync(0xFFFFFFFFu, v, 1);
                v += __shfl_xor_sync(0xFFFFFFFFu, v, 2);
                p[i][rr][o] = v;
            }
    if (tig == 0) {
#pragma unroll
        for (int i = 0; i < 2; i++)
#pragma unroll
            for (int rr = 0; rr < 2; rr++) {
                const int row = wm * 32 + i * 16 + rr * 8 + gid;
#pragma unroll
                for (int o = 0; o < 4; o++)
                    atomicAdd(&sdxy[row][o], p[i][rr][o]);
            }
    }
    __syncthreads();
    for (int i = tid; i < 512; i += 256) {
        const int row = i >> 2, o = i & 3;
        atomicAdd(&dxy[(size_t)(bm + row) * 4 + o], sdxy[row][o]);
    }
}

// ============================================================
// readout: xy += dxy + b2; out[:, step] = xy; dxy = 0
// ============================================================
__global__ void __launch_bounds__(256)
readout_kernel(float* __restrict__ xy, float* __restrict__ dxy,
               const float* __restrict__ b2, float* __restrict__ out, int step)
{
    int i = blockIdx.x * blockDim.x + threadIdx.x;
    if (i < B_) {
        float4 d  = reinterpret_cast<float4*>(dxy)[i];
        float4 xv = reinterpret_cast<float4*>(xy)[i];
        xv.x += d.x + b2[0];
        xv.y += d.y + b2[1];
        xv.z += d.z + b2[2];
        xv.w += d.w + b2[3];
        reinterpret_cast<float4*>(xy)[i] = xv;
        reinterpret_cast<float4*>(out)[(size_t)i * HOR_ + step] = xv;
        reinterpret_cast<float4*>(dxy)[i] = make_float4(0.f, 0.f, 0.f, 0.f);
    }
}

// ============================================================
// Launch
// ============================================================
extern "C" void kernel_launch(void* const* d_in, const int* in_sizes, int n_in,
                              void* d_out, int out_size)
{
    const float* pv   = (const float*)d_in[0];
    const float* ptf  = (const float*)d_in[1];
    const float* w_ih = (const float*)d_in[2];
    const float* w_hh = (const float*)d_in[3];
    const float* b_ih = (const float*)d_in[4];
    const float* b_hh = (const float*)d_in[5];
    const float* w_fc = (const float*)d_in[6];
    const float* b_fc = (const float*)d_in[7];
    const float* w1   = (const float*)d_in[8];
    const float* b1   = (const float*)d_in[9];
    const float* w2   = (const float*)d_in[10];
    const float* b2   = (const float*)d_in[11];
    float* out = (float*)d_out;

    float *h1, *hx, *xy, *dxy;
    __half *h1h, *h2h, *hxh, *hxRh, *ptfh, *whhh, *wfch, *w1h;
    cudaGetSymbolAddress((void**)&h1,   g_h1);
    cudaGetSymbolAddress((void**)&hx,   g_hx);
    cudaGetSymbolAddress((void**)&xy,   g_xy);
    cudaGetSymbolAddress((void**)&dxy,  g_dxy);
    cudaGetSymbolAddress((void**)&h1h,  g_h1h);
    cudaGetSymbolAddress((void**)&h2h,  g_h2h);
    cudaGetSymbolAddress((void**)&hxh,  g_hxh);
    cudaGetSymbolAddress((void**)&hxRh, g_hxRh);
    cudaGetSymbolAddress((void**)&ptfh, g_ptfh);
    cudaGetSymbolAddress((void**)&whhh, g_whhh);
    cudaGetSymbolAddress((void**)&wfch, g_wfch);
    cudaGetSymbolAddress((void**)&w1h,  g_w1h);

    cudaFuncSetAttribute(hh_fused,
        cudaFuncAttributeMaxDynamicSharedMemorySize, HH_SMEM_BYTES);
    cudaFuncSetAttribute(gemm_fc,
        cudaFuncAttributeMaxDynamicSharedMemorySize, GC4_SMEM_BYTES);
    cudaFuncSetAttribute(gemm_mlp,
        cudaFuncAttributeMaxDynamicSharedMemorySize, GC4_SMEM_BYTES);

    // ---- prep ----
    cvt_kernel<<<(3 * H_ * H_ / 4 + 255) / 256, 256>>>(w_hh, whhh, 3 * H_ * H_ / 4);
    cvt_kernel<<<(H_ * 2 * H_ / 4 + 255) / 256, 256>>>(w_fc, wfch, H_ * 2 * H_ / 4);
    cvt_kernel<<<(FF_ * H_ / 4 + 255) / 256, 256>>>(w1, w1h, FF_ * H_ / 4);
    cvt_kernel<<<(B_ * H_ / 4 + 255) / 256, 256>>>(ptf, ptfh, B_ * H_ / 4);
    zero_kernel<<<(B_ * OUT_ + 255) / 256, 256>>>(xy, B_ * OUT_);
    zero_kernel<<<(B_ * OUT_ + 255) / 256, 256>>>(dxy, B_ * OUT_);

    const dim3 gridHH(B_ / 128, H_ / 64);      // (128, 8)
    const dim3 gridFC(B_ / 128, H_ / 128);     // (128, 4)
    const dim3 gridM1(B_ / 128, FF_ / 256);    // (128, 8)

    for (int step = 0; step < HOR_; step++) {
        const __half* hxin_h = (step == 0) ? ptfh : hxh;
        const float*  hxin_f = (step == 0) ? ptf  : hx;

        hh_fused<<<gridHH, 256, HH_SMEM_BYTES>>>(
            hxin_h, whhh, hxin_f, xy, OUT_, w_ih, b_ih, b_hh, h1, h1h);

        hh_fused<<<gridHH, 256, HH_SMEM_BYTES>>>(
            h1h, whhh, h1, pv + step * OUT_, HOR_ * OUT_, w_ih, b_ih, b_hh,
            nullptr, h2h);

        gemm_fc<<<gridFC, 256, GC4_SMEM_BYTES>>>(h1h, h2h, wfch, b_fc,
                                                 hx, hxh, hxRh);

        gemm_mlp<<<gridM1, 256, GC4_SMEM_BYTES>>>(hxRh, w1h, b1, w2, dxy);

        readout_kernel<<<B_ / 256, 256>>>(xy, dxy, b2, out, step);
    }
}

// round 17
// speedup vs baseline: 1.2338x; 1.0008x over previous
#include <cuda_runtime.h>
#include <cuda_fp16.h>
#include <math.h>
#include <stdint.h>

#define B_   16384
#define H_   512
#define FF_  2048
#define OUT_ 4
#define HOR_ 5

// ---- scratch (device globals; no allocation) ----
__device__ float  g_h1[B_ * H_];
__device__ float  g_hx[B_ * H_];
__device__ float  g_xyA[B_ * OUT_];
__device__ float  g_xyB[B_ * OUT_];
__device__ float  g_dxyA[B_ * OUT_];
__device__ float  g_dxyB[B_ * OUT_];
// fp16 copies (GEMM operands)
__device__ __half g_h1h[B_ * H_];
__device__ __half g_h2h[B_ * H_];
__device__ __half g_hxh[B_ * H_];
__device__ __half g_hxRh[B_ * H_];
__device__ __half g_ptfh[B_ * H_];
__device__ __half g_whhh[3 * H_ * H_];
__device__ __half g_wfch[H_ * 2 * H_];
__device__ __half g_w1h[FF_ * H_];

// ============================================================
// helpers
// ============================================================
__device__ __forceinline__ void mma_f16(float c[4], const uint32_t a[4],
                                        const uint32_t b[2]) {
    asm volatile(
        "mma.sync.aligned.m16n8k16.row.col.f32.f16.f16.f32 "
        "{%0,%1,%2,%3}, {%4,%5,%6,%7}, {%8,%9}, {%0,%1,%2,%3};"
        : "+f"(c[0]), "+f"(c[1]), "+f"(c[2]), "+f"(c[3])
        : "r"(a[0]), "r"(a[1]), "r"(a[2]), "r"(a[3]),
          "r"(b[0]), "r"(b[1]));
}

__device__ __forceinline__ void ldsm_x4(uint32_t r[4], uint32_t saddr) {
    asm volatile("ldmatrix.sync.aligned.m8n8.x4.shared.b16 {%0,%1,%2,%3}, [%4];"
                 : "=r"(r[0]), "=r"(r[1]), "=r"(r[2]), "=r"(r[3])
                 : "r"(saddr));
}

__device__ __forceinline__ void cp16(void* smem_ptr, const void* gsrc) {
    uint32_t a = (uint32_t)__cvta_generic_to_shared(smem_ptr);
    asm volatile("cp.async.cg.shared.global [%0], [%1], 16;"
                 :: "r"(a), "l"(gsrc));
}

#define CP_COMMIT() asm volatile("cp.async.commit_group;" ::: "memory")
#define CP_WAIT(n)  asm volatile("cp.async.wait_group %0;" :: "n"(n) : "memory")

__device__ __forceinline__ float fast_sigmoid(float x) {
    return __fdividef(1.f, 1.f + __expf(-x));
}
__device__ __forceinline__ float fast_tanh(float x) {
    float e = __expf(-2.f * x);
    return __fdividef(1.f - e, 1.f + e);
}

// ============================================================
// prep kernels
// ============================================================
__global__ void cvt_kernel(const float* __restrict__ src,
                           __half* __restrict__ dst, int n4) {
    int i = blockIdx.x * blockDim.x + threadIdx.x;
    if (i < n4) {
        float4 v = reinterpret_cast<const float4*>(src)[i];
        reinterpret_cast<__half2*>(dst)[i * 2]     = __floats2half2_rn(v.x, v.y);
        reinterpret_cast<__half2*>(dst)[i * 2 + 1] = __floats2half2_rn(v.z, v.w);
    }
}

__global__ void zero_kernel(float* __restrict__ p, int n) {
    int i = blockIdx.x * blockDim.x + threadIdx.x;
    if (i < n) p[i] = 0.f;
}

#define SMSH 40   // smem row pitch in halves: 32 + 8 pad (80B)

// ============================================================
// Gate-fused HH GEMM.  3-stage cp.async, single sync per tile.
// Optional fused xy-readout path (hh1, steps >= 1):
//   x_row = xy_prev[row] + dxy_prev[row] + b2  (== xy_i)
//   blockIdx.y==0 CTA writes xy_new, out_prev, zeroes dxy_zero.
// Epilogue constants (w_ih / b_ih / b_hh) preloaded to smem.
// ============================================================
#define HH_STAGE_H (320 * SMSH)
#define HH_SMEM_BYTES (3u * HH_STAGE_H * 2u)

__global__ void __launch_bounds__(256, 2)
hh_fused(const __half* __restrict__ Ah, const __half* __restrict__ Whh,
         const float* __restrict__ hf,
         const float* __restrict__ x_plain, int xstride,
         const float* __restrict__ xy_prev, const float* __restrict__ dxy_prev,
         const float* __restrict__ b2,
         float* __restrict__ xy_new, float* __restrict__ out_prev,
         float* __restrict__ dxy_zero,
         const float* __restrict__ w_ih, const float* __restrict__ b_ih,
         const float* __restrict__ b_hh,
         float* __restrict__ hout, __half* __restrict__ houth)
{
    extern __shared__ __half smh[];
    __shared__ float4 s_wih[3][64];
    __shared__ float  s_bih[3][64];
    __shared__ float  s_bhh[3][64];

    const int tid  = threadIdx.x;
    const int warp = tid >> 5;
    const int lane = tid & 31;
    const int gid  = lane >> 2;
    const int tig  = lane & 3;
    const int wm   = warp >> 1;
    const int wn   = warp & 1;
    const int bm   = blockIdx.x * 128;
    const int bn   = blockIdx.y * 64;

    const uint32_t sbase = (uint32_t)__cvta_generic_to_shared(smh);
    const int la_row = ((lane & 8) ? 8 : 0) + (lane & 7);
    const int la_k   = (lane & 16) ? 8 : 0;
    const int lb_n   = ((lane & 16) ? 8 : 0) + (lane & 7);
    const int lb_k   = (lane & 8) ? 8 : 0;

    float acc[3][2][4][4];
#pragma unroll
    for (int g = 0; g < 3; g++)
#pragma unroll
        for (int i = 0; i < 2; i++)
#pragma unroll
            for (int j = 0; j < 4; j++)
#pragma unroll
                for (int r = 0; r < 4; r++) acc[g][i][j][r] = 0.f;

    auto issue = [&](int t) {
        const int s  = t % 3;
        const int k0 = t * 32;
        __half* base = smh + s * HH_STAGE_H;
#pragma unroll
        for (int it = 0; it < 2; it++) {
            int lin = tid + it * 256;
            int row = lin >> 2, j = lin & 3;
            cp16(&base[row * SMSH + j * 8],
                 &Ah[(size_t)(bm + row) * 512 + k0 + j * 8]);
        }
#pragma unroll
        for (int it = 0; it < 3; it++) {
            int lin = tid + it * 256;
            int row = lin >> 2, j = lin & 3;
            int g = row >> 6, lr = row & 63;
            cp16(&base[(128 + row) * SMSH + j * 8],
                 &Whh[(size_t)(g * 512 + bn + lr) * 512 + k0 + j * 8]);
        }
        CP_COMMIT();
    };

    issue(0); issue(1);

    // preload epilogue constants into smem (overlaps with cp.async)
    for (int idx = tid; idx < 192; idx += 256) {
        int g = idx >> 6, c = idx & 63;
        int cc = g * 512 + bn + c;
        s_wih[g][c] = *reinterpret_cast<const float4*>(&w_ih[(size_t)cc * 4]);
        s_bih[g][c] = b_ih[cc];
        s_bhh[g][c] = b_hh[cc];
    }
    // zero the dxy buffer this step's MLP will use (no reader this launch)
    if (dxy_zero && blockIdx.y == 0 && tid < 128) {
        reinterpret_cast<float4*>(dxy_zero)[bm + tid]
            = make_float4(0.f, 0.f, 0.f, 0.f);
    }

    for (int t = 0; t < 16; t++) {
        const int rem = 15 - t;
        if (rem >= 1) CP_WAIT(1);
        else          CP_WAIT(0);
        __syncthreads();
        if (t + 2 < 16) issue(t + 2);

        const uint32_t st = sbase + (uint32_t)((t % 3) * HH_STAGE_H) * 2u;

#pragma unroll
        for (int kk = 0; kk < 2; kk++) {
            uint32_t afr[2][4];
#pragma unroll
            for (int i = 0; i < 2; i++)
                ldsm_x4(afr[i], st + (uint32_t)(
                    (wm * 32 + i * 16 + la_row) * SMSH + kk * 16 + la_k) * 2u);
#pragma unroll
            for (int g = 0; g < 3; g++) {
                uint32_t bfr[4][2];
#pragma unroll
                for (int jp = 0; jp < 2; jp++) {
                    uint32_t r[4];
                    ldsm_x4(r, st + (uint32_t)(
                        (128 + g * 64 + wn * 32 + jp * 16 + lb_n) * SMSH
                        + kk * 16 + lb_k) * 2u);
                    bfr[jp * 2][0]     = r[0]; bfr[jp * 2][1]     = r[1];
                    bfr[jp * 2 + 1][0] = r[2]; bfr[jp * 2 + 1][1] = r[3];
                }
#pragma unroll
                for (int i = 0; i < 2; i++)
#pragma unroll
                    for (int j = 0; j < 4; j++)
                        mma_f16(acc[g][i][j], afr[i], bfr[j]);
            }
        }
    }

    // ---- fused gate epilogue ----
    float4 b2v = make_float4(0.f, 0.f, 0.f, 0.f);
    if (xy_prev) b2v = *reinterpret_cast<const float4*>(b2);

#pragma unroll
    for (int i = 0; i < 2; i++) {
        const int r0 = bm + wm * 32 + i * 16 + gid;
        const int r1 = r0 + 8;
        float4 xv0, xv1;
        if (xy_prev) {
            float4 a0 = reinterpret_cast<const float4*>(xy_prev)[r0];
            float4 d0 = reinterpret_cast<const float4*>(dxy_prev)[r0];
            float4 a1 = reinterpret_cast<const float4*>(xy_prev)[r1];
            float4 d1 = reinterpret_cast<const float4*>(dxy_prev)[r1];
            xv0 = make_float4(a0.x + d0.x + b2v.x, a0.y + d0.y + b2v.y,
                              a0.z + d0.z + b2v.z, a0.w + d0.w + b2v.w);
            xv1 = make_float4(a1.x + d1.x + b2v.x, a1.y + d1.y + b2v.y,
                              a1.z + d1.z + b2v.z, a1.w + d1.w + b2v.w);
            // unique writer per row: bn CTA 0, wn==0, tig==0
            if (blockIdx.y == 0 && wn == 0 && tig == 0) {
                reinterpret_cast<float4*>(xy_new)[r0] = xv0;
                reinterpret_cast<float4*>(xy_new)[r1] = xv1;
                *reinterpret_cast<float4*>(&out_prev[(size_t)r0 * (HOR_ * OUT_)]) = xv0;
                *reinterpret_cast<float4*>(&out_prev[(size_t)r1 * (HOR_ * OUT_)]) = xv1;
            }
        } else if (x_plain) {
            xv0 = *reinterpret_cast<const float4*>(&x_plain[(size_t)r0 * xstride]);
            xv1 = *reinterpret_cast<const float4*>(&x_plain[(size_t)r1 * xstride]);
        } else {
            xv0 = make_float4(0.f, 0.f, 0.f, 0.f);
            xv1 = xv0;
        }
#pragma unroll
        for (int j = 0; j < 4; j++) {
            const int col  = bn + wn * 32 + j * 8 + tig * 2;
            const int lcol = wn * 32 + j * 8 + tig * 2;
            const float2 hp0 = *reinterpret_cast<const float2*>(&hf[(size_t)r0 * 512 + col]);
            const float2 hp1 = *reinterpret_cast<const float2*>(&hf[(size_t)r1 * 512 + col]);
            float res[2][2];
#pragma unroll
            for (int c = 0; c < 2; c++) {
                const int lc = lcol + c;
                const float4 wr  = s_wih[0][lc];
                const float4 wz  = s_wih[1][lc];
                const float4 wnn = s_wih[2][lc];
                const float bir = s_bih[0][lc], biz = s_bih[1][lc], bin = s_bih[2][lc];
                const float bhr = s_bhh[0][lc], bhz = s_bhh[1][lc], bhn = s_bhh[2][lc];
#pragma unroll
                for (int rr = 0; rr < 2; rr++) {
                    const float4 xv = rr ? xv1 : xv0;
                    float gir = bir + xv.x*wr.x + xv.y*wr.y + xv.z*wr.z + xv.w*wr.w;
                    float giz = biz + xv.x*wz.x + xv.y*wz.y + xv.z*wz.z + xv.w*wz.w;
                    float gin = bin + xv.x*wnn.x + xv.y*wnn.y + xv.z*wnn.z + xv.w*wnn.w;
                    float ghr = acc[0][i][j][rr * 2 + c] + bhr;
                    float ghz = acc[1][i][j][rr * 2 + c] + bhz;
                    float ghn = acc[2][i][j][rr * 2 + c] + bhn;
                    float rg = fast_sigmoid(gir + ghr);
                    float zg = fast_sigmoid(giz + ghz);
                    float ng = fast_tanh(gin + rg * ghn);
                    float hprev = rr ? (c ? hp1.y : hp1.x) : (c ? hp0.y : hp0.x);
                    res[rr][c] = (1.f - zg) * ng + zg * hprev;
                }
            }
            if (hout) {
                *reinterpret_cast<float2*>(&hout[(size_t)r0 * 512 + col])
                    = make_float2(res[0][0], res[0][1]);
                *reinterpret_cast<float2*>(&hout[(size_t)r1 * 512 + col])
                    = make_float2(res[1][0], res[1][1]);
            }
            *reinterpret_cast<__half2*>(&houth[(size_t)r0 * 512 + col])
                = __floats2half2_rn(res[0][0], res[0][1]);
            *reinterpret_cast<__half2*>(&houth[(size_t)r1 * 512 + col])
                = __floats2half2_rn(res[1][0], res[1][1]);
        }
    }
}

// ============================================================
// fc GEMM. 4-stage cp.async, single sync per tile.
// TRIPLE write: hx fp32, hxh fp16, hxRh relu fp16.
// ============================================================
#define TILE_H (128 * SMSH)
#define GC4_SMEM_BYTES (8u * TILE_H * 2u)

__global__ void __launch_bounds__(256, 2)
gemm_fc(const __half* __restrict__ A, const __half* __restrict__ A2,
        const __half* __restrict__ W, const float* __restrict__ bias,
        float* __restrict__ C, __half* __restrict__ Ch, __half* __restrict__ Chr)
{
    extern __shared__ __half smh[];
    const int K = 1024, N = 512;

    const int tid  = threadIdx.x;
    const int warp = tid >> 5;
    const int lane = tid & 31;
    const int gid  = lane >> 2;
    const int tig  = lane & 3;
    const int wm   = warp >> 1;
    const int wn   = warp & 1;
    const int bm   = blockIdx.x * 128;
    const int bn   = blockIdx.y * 128;

    const uint32_t sbase = (uint32_t)__cvta_generic_to_shared(smh);
    const int la_row = ((lane & 8) ? 8 : 0) + (lane & 7);
    const int la_k   = (lane & 16) ? 8 : 0;
    const int lb_n   = ((lane & 16) ? 8 : 0) + (lane & 7);
    const int lb_k   = (lane & 8) ? 8 : 0;

    float acc[2][8][4];
#pragma unroll
    for (int i = 0; i < 2; i++)
#pragma unroll
        for (int j = 0; j < 8; j++)
#pragma unroll
            for (int r = 0; r < 4; r++) acc[i][j][r] = 0.f;

    auto issue_tile = [&](int t) {
        const int s  = t & 3;
        const int k0 = t * 32;
        __half* sAh = smh + s * TILE_H;
        __half* sWh = smh + (4 + s) * TILE_H;
#pragma unroll
        for (int it = 0; it < 2; it++) {
            int lin = tid + it * 256;
            int row = lin >> 2, j = lin & 3;
            cp16(&sWh[row * SMSH + j * 8], &W[(size_t)(bn + row) * K + k0 + j * 8]);
            const __half* asrc = (k0 < 512)
                ? &A [(size_t)(bm + row) * 512 + k0 + j * 8]
                : &A2[(size_t)(bm + row) * 512 + (k0 - 512) + j * 8];
            cp16(&sAh[row * SMSH + j * 8], asrc);
        }
        CP_COMMIT();
    };

    const int T = K >> 5;
    issue_tile(0); issue_tile(1); issue_tile(2);

    for (int t = 0; t < T; t++) {
        const int rem = T - 1 - t;
        if (rem >= 2)      CP_WAIT(2);
        else if (rem == 1) CP_WAIT(1);
        else               CP_WAIT(0);
        __syncthreads();
        if (t + 3 < T) issue_tile(t + 3);

        const uint32_t stA = sbase + (uint32_t)((t & 3) * TILE_H) * 2u;
        const uint32_t stW = sbase + (uint32_t)((4 + (t & 3)) * TILE_H) * 2u;

#pragma unroll
        for (int kk = 0; kk < 2; kk++) {
            uint32_t afr[2][4];
#pragma unroll
            for (int i = 0; i < 2; i++)
                ldsm_x4(afr[i], stA + (uint32_t)(
                    (wm * 32 + i * 16 + la_row) * SMSH + kk * 16 + la_k) * 2u);
            uint32_t bfr[8][2];
#pragma unroll
            for (int jp = 0; jp < 4; jp++) {
                uint32_t r[4];
                ldsm_x4(r, stW + (uint32_t)(
                    (wn * 64 + jp * 16 + lb_n) * SMSH + kk * 16 + lb_k) * 2u);
                bfr[jp * 2][0]     = r[0]; bfr[jp * 2][1]     = r[1];
                bfr[jp * 2 + 1][0] = r[2]; bfr[jp * 2 + 1][1] = r[3];
            }
#pragma unroll
            for (int i = 0; i < 2; i++)
#pragma unroll
                for (int j = 0; j < 8; j++)
                    mma_f16(acc[i][j], afr[i], bfr[j]);
        }
    }

#pragma unroll
    for (int i = 0; i < 2; i++) {
        int row0 = bm + wm * 32 + i * 16 + gid;
#pragma unroll
        for (int j = 0; j < 8; j++) {
            int col = bn + wn * 64 + j * 8 + tig * 2;
            float b0 = bias[col], b1v = bias[col + 1];
            float v0 = acc[i][j][0] + b0;
            float v1 = acc[i][j][1] + b1v;
            float v2 = acc[i][j][2] + b0;
            float v3 = acc[i][j][3] + b1v;
            *reinterpret_cast<float2*>(&C[(size_t)row0 * N + col]) = make_float2(v0, v1);
            *reinterpret_cast<float2*>(&C[(size_t)(row0 + 8) * N + col]) = make_float2(v2, v3);
            *reinterpret_cast<__half2*>(&Ch[(size_t)row0 * N + col])
                = __floats2half2_rn(v0, v1);
            *reinterpret_cast<__half2*>(&Ch[(size_t)(row0 + 8) * N + col])
                = __floats2half2_rn(v2, v3);
            *reinterpret_cast<__half2*>(&Chr[(size_t)row0 * N + col])
                = __floats2half2_rn(fmaxf(v0, 0.f), fmaxf(v1, 0.f));
            *reinterpret_cast<__half2*>(&Chr[(size_t)(row0 + 8) * N + col])
                = __floats2half2_rn(fmaxf(v2, 0.f), fmaxf(v3, 0.f));
        }
    }
}

// ============================================================
// MLP GEMM fused with w2 contraction, 2 n-tiles per CTA, 4-stage,
// single sync per tile.  grid (B/128, FF/256).
// ============================================================
__global__ void __launch_bounds__(256, 2)
gemm_mlp(const __half* __restrict__ A, const __half* __restrict__ W,
         const float* __restrict__ b1g, const float* __restrict__ w2,
         float* __restrict__ dxy)
{
    extern __shared__ __half smh[];
    __shared__ float sw2[4][256];
    __shared__ float sdxy[128][4];
    const int K = 512;

    const int tid  = threadIdx.x;
    const int warp = tid >> 5;
    const int lane = tid & 31;
    const int gid  = lane >> 2;
    const int tig  = lane & 3;
    const int wm   = warp >> 1;
    const int wn   = warp & 1;
    const int bm   = blockIdx.x * 128;
    const int bn   = blockIdx.y * 256;

    const uint32_t sbase = (uint32_t)__cvta_generic_to_shared(smh);
    const int la_row = ((lane & 8) ? 8 : 0) + (lane & 7);
    const int la_k   = (lane & 16) ? 8 : 0;
    const int lb_n   = ((lane & 16) ? 8 : 0) + (lane & 7);
    const int lb_k   = (lane & 8) ? 8 : 0;

    for (int i = tid; i < 4 * 256; i += 256)
        sw2[i >> 8][i & 255] = w2[(size_t)(i >> 8) * 2048 + bn + (i & 255)];
    for (int i = tid; i < 512; i += 256)
        reinterpret_cast<float*>(sdxy)[i] = 0.f;

    auto issue_tile = [&](int tt) {
        const int s  = tt & 3;
        const int nt = tt >> 4;
        const int k0 = (tt & 15) * 32;
        __half* sAh = smh + s * TILE_H;
        __half* sWh = smh + (4 + s) * TILE_H;
#pragma unroll
        for (int it = 0; it < 2; it++) {
            int lin = tid + it * 256;
            int row = lin >> 2, j = lin & 3;
            cp16(&sWh[row * SMSH + j * 8],
                 &W[(size_t)(bn + nt * 128 + row) * K + k0 + j * 8]);
            cp16(&sAh[row * SMSH + j * 8],
                 &A[(size_t)(bm + row) * K + k0 + j * 8]);
        }
        CP_COMMIT();
    };

    issue_tile(0); issue_tile(1); issue_tile(2);

    float p[2][2][4];
#pragma unroll
    for (int i = 0; i < 2; i++)
#pragma unroll
        for (int rr = 0; rr < 2; rr++)
#pragma unroll
            for (int o = 0; o < 4; o++) p[i][rr][o] = 0.f;

    float acc[2][8][4];

    for (int tt = 0; tt < 32; tt++) {
        const int rem = 31 - tt;
        if (rem >= 2)      CP_WAIT(2);
        else if (rem == 1) CP_WAIT(1);
        else               CP_WAIT(0);
        __syncthreads();
        if (tt + 3 < 32) issue_tile(tt + 3);

        if ((tt & 15) == 0) {
#pragma unroll
            for (int i = 0; i < 2; i++)
#pragma unroll
                for (int j = 0; j < 8; j++)
#pragma unroll
                    for (int r = 0; r < 4; r++) acc[i][j][r] = 0.f;
        }

        const uint32_t stA = sbase + (uint32_t)((tt & 3) * TILE_H) * 2u;
        const uint32_t stW = sbase + (uint32_t)((4 + (tt & 3)) * TILE_H) * 2u;

#pragma unroll
        for (int kk = 0; kk < 2; kk++) {
            uint32_t afr[2][4];
#pragma unroll
            for (int i = 0; i < 2; i++)
                ldsm_x4(afr[i], stA + (uint32_t)(
                    (wm * 32 + i * 16 + la_row) * SMSH + kk * 16 + la_k) * 2u);
            uint32_t bfr[8][2];
#pragma unroll
            for (int jp = 0; jp < 4; jp++) {
                uint32_t r[4];
                ldsm_x4(r, stW + (uint32_t)(
                    (wn * 64 + jp * 16 + lb_n) * SMSH + kk * 16 + lb_k) * 2u);
                bfr[jp * 2][0]     = r[0]; bfr[jp * 2][1]     = r[1];
                bfr[jp * 2 + 1][0] = r[2]; bfr[jp * 2 + 1][1] = r[3];
            }
#pragma unroll
            for (int i = 0; i < 2; i++)
#pragma unroll
                for (int j = 0; j < 8; j++)
                    mma_f16(acc[i][j], afr[i], bfr[j]);
        }

        if ((tt & 15) == 15) {
            const int nb = (tt >> 4) * 128;
#pragma unroll
            for (int i = 0; i < 2; i++)
#pragma unroll
                for (int j = 0; j < 8; j++) {
                    const int lc = wn * 64 + j * 8 + tig * 2;
                    const float bb0 = b1g[bn + nb + lc];
                    const float bb1 = b1g[bn + nb + lc + 1];
                    const float a00 = fmaxf(acc[i][j][0] + bb0, 0.f);
                    const float a01 = fmaxf(acc[i][j][1] + bb1, 0.f);
                    const float a10 = fmaxf(acc[i][j][2] + bb0, 0.f);
                    const float a11 = fmaxf(acc[i][j][3] + bb1, 0.f);
#pragma unroll
                    for (int o = 0; o < 4; o++) {
                        const float w0 = sw2[o][nb + lc];
                        const float w1 = sw2[o][nb + lc + 1];
                        p[i][0][o] += a00 * w0 + a01 * w1;
                        p[i][1][o] += a10 * w0 + a11 * w1;
                    }
                }
        }
    }

    // ---- reduce and atomically accumulate ----
#pragma unroll
    for (int i = 0; i < 2; i++)
#pragma unroll
        for (int rr = 0; rr < 2; rr++)
#pragma unroll
            for (int o = 0; o < 4; o++) {
                float v = p[i][rr][o];
                v += __shfl_xor_sync(0xFFFFFFFFu, v, 1);
                v += __shfl_xor_sync(0xFFFFFFFFu, v, 2);
                p[i][rr][o] = v;
            }
    if (tig == 0) {
#pragma unroll
        for (int i = 0; i < 2; i++)
#pragma unroll
            for (int rr = 0; rr < 2; rr++) {
                const int row = wm * 32 + i * 16 + rr * 8 + gid;
#pragma unroll
                for (int o = 0; o < 4; o++)
                    atomicAdd(&sdxy[row][o], p[i][rr][o]);
            }
    }
    __syncthreads();
    for (int i = tid; i < 512; i += 256) {
        const int row = i >> 2, o = i & 3;
        atomicAdd(&dxy[(size_t)(bm + row) * 4 + o], sdxy[row][o]);
    }
}

// ============================================================
// final: out[:, HOR-1] = xy_last + dxy_last + b2
// ============================================================
__global__ void __launch_bounds__(256)
final_out_kernel(const float* __restrict__ xy, const float* __restrict__ dxy,
                 const float* __restrict__ b2, float* __restrict__ out)
{
    int i = blockIdx.x * blockDim.x + threadIdx.x;
    if (i < B_) {
        float4 d  = reinterpret_cast<const float4*>(dxy)[i];
        float4 xv = reinterpret_cast<const float4*>(xy)[i];
        xv.x += d.x + b2[0];
        xv.y += d.y + b2[1];
        xv.z += d.z + b2[2];
        xv.w += d.w + b2[3];
        *reinterpret_cast<float4*>(&out[(size_t)i * (HOR_ * OUT_) + (HOR_ - 1) * OUT_]) = xv;
    }
}

// ============================================================
// Launch
// ============================================================
extern "C" void kernel_launch(void* const* d_in, const int* in_sizes, int n_in,
                              void* d_out, int out_size)
{
    const float* pv   = (const float*)d_in[0];
    const float* ptf  = (const float*)d_in[1];
    const float* w_ih = (const float*)d_in[2];
    const float* w_hh = (const float*)d_in[3];
    const float* b_ih = (const float*)d_in[4];
    const float* b_hh = (const float*)d_in[5];
    const float* w_fc = (const float*)d_in[6];
    const float* b_fc = (const float*)d_in[7];
    const float* w1   = (const float*)d_in[8];
    const float* b1   = (const float*)d_in[9];
    const float* w2   = (const float*)d_in[10];
    const float* b2   = (const float*)d_in[11];
    float* out = (float*)d_out;

    float *h1, *hx, *xyA, *xyB, *dxyA, *dxyB;
    __half *h1h, *h2h, *hxh, *hxRh, *ptfh, *whhh, *wfch, *w1h;
    cudaGetSymbolAddress((void**)&h1,   g_h1);
    cudaGetSymbolAddress((void**)&hx,   g_hx);
    cudaGetSymbolAddress((void**)&xyA,  g_xyA);
    cudaGetSymbolAddress((void**)&xyB,  g_xyB);
    cudaGetSymbolAddress((void**)&dxyA, g_dxyA);
    cudaGetSymbolAddress((void**)&dxyB, g_dxyB);
    cudaGetSymbolAddress((void**)&h1h,  g_h1h);
    cudaGetSymbolAddress((void**)&h2h,  g_h2h);
    cudaGetSymbolAddress((void**)&hxh,  g_hxh);
    cudaGetSymbolAddress((void**)&hxRh, g_hxRh);
    cudaGetSymbolAddress((void**)&ptfh, g_ptfh);
    cudaGetSymbolAddress((void**)&whhh, g_whhh);
    cudaGetSymbolAddress((void**)&wfch, g_wfch);
    cudaGetSymbolAddress((void**)&w1h,  g_w1h);

    float* xyb[2]  = {xyA,  xyB};
    float* dxyb[2] = {dxyA, dxyB};

    cudaFuncSetAttribute(hh_fused,
        cudaFuncAttributeMaxDynamicSharedMemorySize, HH_SMEM_BYTES);
    cudaFuncSetAttribute(gemm_fc,
        cudaFuncAttributeMaxDynamicSharedMemorySize, GC4_SMEM_BYTES);
    cudaFuncSetAttribute(gemm_mlp,
        cudaFuncAttributeMaxDynamicSharedMemorySize, GC4_SMEM_BYTES);

    // ---- prep ----
    cvt_kernel<<<(3 * H_ * H_ / 4 + 255) / 256, 256>>>(w_hh, whhh, 3 * H_ * H_ / 4);
    cvt_kernel<<<(H_ * 2 * H_ / 4 + 255) / 256, 256>>>(w_fc, wfch, H_ * 2 * H_ / 4);
    cvt_kernel<<<(FF_ * H_ / 4 + 255) / 256, 256>>>(w1, w1h, FF_ * H_ / 4);
    cvt_kernel<<<(B_ * H_ / 4 + 255) / 256, 256>>>(ptf, ptfh, B_ * H_ / 4);
    zero_kernel<<<(B_ * OUT_ + 255) / 256, 256>>>(xyA, B_ * OUT_);   // xy_0 = 0
    zero_kernel<<<(B_ * OUT_ + 255) / 256, 256>>>(dxyA, B_ * OUT_);  // mlp step0 target

    const dim3 gridHH(B_ / 128, H_ / 64);      // (128, 8)
    const dim3 gridFC(B_ / 128, H_ / 128);     // (128, 4)
    const dim3 gridM1(B_ / 128, FF_ / 256);    // (128, 8)

    for (int step = 0; step < HOR_; step++) {
        const __half* hxin_h = (step == 0) ? ptfh : hxh;
        const float*  hxin_f = (step == 0) ? ptf  : hx;

        // cell 1 (fused gate + fused xy readout for step>=1)
        if (step == 0) {
            hh_fused<<<gridHH, 256, HH_SMEM_BYTES>>>(
                hxin_h, whhh, hxin_f,
                nullptr, 0,                      // x = 0 (xy_0)
                nullptr, nullptr, nullptr,       // no fused readout
                nullptr, nullptr, nullptr,
                w_ih, b_ih, b_hh, h1, h1h);
        } else {
            hh_fused<<<gridHH, 256, HH_SMEM_BYTES>>>(
                hxin_h, whhh, hxin_f,
                nullptr, 0,
                xyb[(step - 1) & 1], dxyb[(step - 1) & 1], b2,
                xyb[step & 1], out + (size_t)(step - 1) * OUT_, dxyb[step & 1],
                w_ih, b_ih, b_hh, h1, h1h);
        }

        // cell 2
        hh_fused<<<gridHH, 256, HH_SMEM_BYTES>>>(
            h1h, whhh, h1,
            pv + step * OUT_, HOR_ * OUT_,
            nullptr, nullptr, nullptr, nullptr, nullptr, nullptr,
            w_ih, b_ih, b_hh, nullptr, h2h);

        gemm_fc<<<gridFC, 256, GC4_SMEM_BYTES>>>(h1h, h2h, wfch, b_fc,
                                                 hx, hxh, hxRh);

        gemm_mlp<<<gridM1, 256, GC4_SMEM_BYTES>>>(hxRh, w1h, b1, w2,
                                                  dxyb[step & 1]);
    }

    // out[:, HOR-1] = xy_{HOR-1} + dxy_{HOR-1} + b2
    final_out_kernel<<<B_ / 256, 256>>>(xyb[(HOR_ - 1) & 1], dxyb[(HOR_ - 1) & 1],
                                        b2, out);
}